// round 8
// baseline (speedup 1.0000x reference)
#include <cuda_runtime.h>
#include <cuda_bf16.h>
#include <cstdint>

#define BB 32
#define SS 4096
#define DD 64
#define KCC 256

// ------------------------- device global scratch ---------------------------
__device__ __nv_bfloat16 g_Wh[2 * KCC * SS];       // [proj][kc][s] hi
__device__ __nv_bfloat16 g_Wl[2 * KCC * SS];       // lo
__device__ __nv_bfloat16 g_Keh[BB * KCC * DD];     // [b][kc][d] hi  (= Ke^T)
__device__ __nv_bfloat16 g_Kel[BB * KCC * DD];     // lo
__device__ __nv_bfloat16 g_Vfh[BB * KCC * DD];     // [b][kc][d] hi
__device__ __nv_bfloat16 g_Vfl[BB * KCC * DD];     // lo

// ------------------------------ helpers ------------------------------------
__device__ __forceinline__ uint32_t smem_u32(const void* p) {
    uint32_t a;
    asm("{ .reg .u64 t; cvta.to.shared.u64 t, %1; cvt.u32.u64 %0, t; }"
        : "=r"(a) : "l"(p));
    return a;
}
#define SW128(x) ((x) ^ (((x) >> 3) & 0x70))

__device__ __forceinline__ void cp16(uint32_t dst, const void* src) {
    asm volatile("cp.async.cg.shared.global [%0], [%1], 16;"
                 :: "r"(dst), "l"(src) : "memory");
}
__device__ __forceinline__ void cp_commit() {
    asm volatile("cp.async.commit_group;" ::: "memory");
}
template <int N>
__device__ __forceinline__ void cp_wait() {
    asm volatile("cp.async.wait_group %0;" :: "n"(N) : "memory");
}
__device__ __forceinline__ void ldm_x4(uint32_t* r, uint32_t addr) {
    asm volatile("ldmatrix.sync.aligned.m8n8.x4.shared.b16 {%0,%1,%2,%3}, [%4];"
                 : "=r"(r[0]), "=r"(r[1]), "=r"(r[2]), "=r"(r[3]) : "r"(addr));
}
__device__ __forceinline__ void ldm_x4_t(uint32_t* r, uint32_t addr) {
    asm volatile("ldmatrix.sync.aligned.m8n8.x4.trans.shared.b16 {%0,%1,%2,%3}, [%4];"
                 : "=r"(r[0]), "=r"(r[1]), "=r"(r[2]), "=r"(r[3]) : "r"(addr));
}
__device__ __forceinline__ void mma_bf16(
    float* c, const uint32_t* a, uint32_t b0, uint32_t b1) {
    asm volatile(
        "mma.sync.aligned.m16n8k16.row.col.f32.bf16.bf16.f32 "
        "{%0,%1,%2,%3}, {%4,%5,%6,%7}, {%8,%9}, {%0,%1,%2,%3};"
        : "+f"(c[0]), "+f"(c[1]), "+f"(c[2]), "+f"(c[3])
        : "r"(a[0]), "r"(a[1]), "r"(a[2]), "r"(a[3]), "r"(b0), "r"(b1));
}
__device__ __forceinline__ uint32_t packbf(float lo, float hi) {
    uint32_t r;
    asm("cvt.rn.bf16x2.f32 %0, %1, %2;" : "=r"(r) : "f"(hi), "f"(lo));
    return r;
}
__device__ __forceinline__ float bfres(float v) {   // v - bf16(v)
    return v - __bfloat162float(__float2bfloat16(v));
}

// ---------------------------------------------------------------------------
// conv_w: E_w / F_w (fp32 [256][4096]) -> bf16 hi/lo, same layout.
// ---------------------------------------------------------------------------
__global__ __launch_bounds__(256) void conv_w_kernel(
    const float* __restrict__ Ew, const float* __restrict__ Fw)
{
    const int y = blockIdx.y;
    const float4* src = reinterpret_cast<const float4*>(y ? Fw : Ew);
    const int i = blockIdx.x * 256 + threadIdx.x;
    float4 v = src[i];
    __nv_bfloat16 h0 = __float2bfloat16(v.x), h1 = __float2bfloat16(v.y),
                  h2 = __float2bfloat16(v.z), h3 = __float2bfloat16(v.w);
    __nv_bfloat16 l0 = __float2bfloat16(v.x - __bfloat162float(h0));
    __nv_bfloat16 l1 = __float2bfloat16(v.y - __bfloat162float(h1));
    __nv_bfloat16 l2 = __float2bfloat16(v.z - __bfloat162float(h2));
    __nv_bfloat16 l3 = __float2bfloat16(v.w - __bfloat162float(h3));
    __nv_bfloat162* oh = reinterpret_cast<__nv_bfloat162*>(
        g_Wh + (size_t)y * KCC * SS) + 2 * i;
    __nv_bfloat162* ol = reinterpret_cast<__nv_bfloat162*>(
        g_Wl + (size_t)y * KCC * SS) + 2 * i;
    oh[0] = __halves2bfloat162(h0, h1);
    oh[1] = __halves2bfloat162(h2, h3);
    ol[0] = __halves2bfloat162(l0, l1);
    ol[1] = __halves2bfloat162(l2, l3);
}

// ---------------------------------------------------------------------------
// proj_mma: mma.sync bf16 3-split GEMM, 2 batches per CTA (W stream shared).
//   D[bb][kc][d] = sum_s W[kc][s] * X[bb][s][d]  (M=128, N=64, K=4096, bb=2)
// Grid (2 kc, 16 b-pairs, 2 proj) = 64 CTAs. Block 256.
// SMEM: W 4 x 32KB @0 | X 2 stages x 2 batches x 16KB @131072. Total 192KB.
// ---------------------------------------------------------------------------
__global__ __launch_bounds__(256) void proj_mma_kernel(
    const float* __restrict__ Kf, const float* __restrict__ Vf,
    const float* __restrict__ E_b, const float* __restrict__ F_b)
{
    extern __shared__ char sm[];
    const uint32_t smb = smem_u32(sm);
    const int tid = threadIdx.x, wid = tid >> 5, lane = tid & 31;
    const int kc0 = blockIdx.x * 128, bp = blockIdx.y, proj = blockIdx.z;
    const int mw = wid >> 2, nw = wid & 3;
    const int g = lane >> 2, q = lane & 3;

    const __nv_bfloat16* Wh = g_Wh + ((size_t)proj * KCC + kc0) * SS;
    const __nv_bfloat16* Wl = g_Wl + ((size_t)proj * KCC + kc0) * SS;
    const float* Xsrc = proj ? Vf : Kf;
    const float* Xb[2] = { Xsrc + (size_t)(2 * bp) * SS * DD,
                           Xsrc + (size_t)(2 * bp + 1) * SS * DD };

    float acc[2][4][2][4];   // [batch][mf][nf][c]
#pragma unroll
    for (int bb = 0; bb < 2; bb++)
#pragma unroll
        for (int mf = 0; mf < 4; mf++)
#pragma unroll
            for (int nf = 0; nf < 2; nf++)
#pragma unroll
                for (int i = 0; i < 4; i++) acc[bb][mf][nf][i] = 0.f;

    const int NC = SS / 64;   // 64 chunks

    auto load_w = [&](int c) {
        const uint32_t buf = smb + (c & 3) * 32768;
#pragma unroll
        for (int idx = tid; idx < 1024; idx += 256) {
            int row = idx >> 3, s16 = idx & 7;
            size_t so = (size_t)row * SS + c * 64 + s16 * 8;
            uint32_t bo = SW128((uint32_t)(row * 128 + s16 * 16));
            cp16(buf + bo,         Wh + so);
            cp16(buf + 16384 + bo, Wl + so);
        }
        cp_commit();
    };

    // X chunk: per batch, 64 s-rows x 64 d fp32; thread owns segs tid, tid+256
    float4 xr[2][2][2];   // [batch][u][half]
    auto ldx = [&](int c) {
#pragma unroll
        for (int bb = 0; bb < 2; bb++)
#pragma unroll
            for (int u = 0; u < 2; u++) {
                int seg = tid + u * 256;
                int row = seg >> 3, s16 = seg & 7;
                const float* p = Xb[bb] + (size_t)(c * 64 + row) * DD + s16 * 8;
                xr[bb][u][0] = *reinterpret_cast<const float4*>(p);
                xr[bb][u][1] = *reinterpret_cast<const float4*>(p + 4);
            }
    };
    auto stx = [&](int stage) {
#pragma unroll
        for (int bb = 0; bb < 2; bb++) {
            char* xbase = sm + 131072 + stage * 32768 + bb * 16384;
#pragma unroll
            for (int u = 0; u < 2; u++) {
                int seg = tid + u * 256;
                int row = seg >> 3, s16 = seg & 7;
                uint32_t bo = SW128((uint32_t)(row * 128 + s16 * 16));
                float4 v0 = xr[bb][u][0], v1 = xr[bb][u][1];
                uint4 h, l;
                h.x = packbf(v0.x, v0.y); h.y = packbf(v0.z, v0.w);
                h.z = packbf(v1.x, v1.y); h.w = packbf(v1.z, v1.w);
                l.x = packbf(bfres(v0.x), bfres(v0.y));
                l.y = packbf(bfres(v0.z), bfres(v0.w));
                l.z = packbf(bfres(v1.x), bfres(v1.y));
                l.w = packbf(bfres(v1.z), bfres(v1.w));
                *reinterpret_cast<uint4*>(xbase + bo)        = h;
                *reinterpret_cast<uint4*>(xbase + 8192 + bo) = l;
            }
        }
    };

    load_w(0); load_w(1); load_w(2);
    ldx(0);

    for (int c = 0; c < NC; c++) {
        if (c + 3 < NC) { load_w(c + 3); cp_wait<3>(); }
        else            { cp_wait<0>(); }

        stx(c & 1);
        if (c + 1 < NC) ldx(c + 1);
        __syncthreads();

        const uint32_t wbuf = smb + (c & 3) * 32768;
        const uint32_t Ah = wbuf, Al = wbuf + 16384;
        const uint32_t xs = smb + 131072 + (c & 1) * 32768;
        const int lr = lane & 15, lc = (lane >> 4) * 16;

#pragma unroll
        for (int kk = 0; kk < 4; kk++) {
            uint32_t bh[2][4], bl[2][4];
            uint32_t boff = SW128((uint32_t)((kk * 16 + lr) * 128 + nw * 32 + lc));
#pragma unroll
            for (int bb = 0; bb < 2; bb++) {
                ldm_x4_t(bh[bb], xs + bb * 16384 + boff);
                ldm_x4_t(bl[bb], xs + bb * 16384 + 8192 + boff);
            }
#pragma unroll
            for (int mf = 0; mf < 4; mf++) {
                uint32_t ah[4], al[4];
                uint32_t off = SW128((uint32_t)(
                    (mw * 64 + mf * 16 + lr) * 128 + kk * 32 + lc));
                ldm_x4(ah, Ah + off);
                ldm_x4(al, Al + off);
#pragma unroll
                for (int bb = 0; bb < 2; bb++)
#pragma unroll
                    for (int nf = 0; nf < 2; nf++) {
                        mma_bf16(acc[bb][mf][nf], ah, bh[bb][2 * nf], bh[bb][2 * nf + 1]);
                        mma_bf16(acc[bb][mf][nf], al, bh[bb][2 * nf], bh[bb][2 * nf + 1]);
                        mma_bf16(acc[bb][mf][nf], ah, bl[bb][2 * nf], bl[bb][2 * nf + 1]);
                    }
            }
        }
        __syncthreads();
    }

    // ---- epilogue: bias add, bf16 hi/lo split, store [b][kc][d] ----
    const float* bias = proj ? F_b : E_b;
#pragma unroll
    for (int bb = 0; bb < 2; bb++) {
        const int b = 2 * bp + bb;
        __nv_bfloat16* oh = (proj ? g_Vfh : g_Keh) + ((size_t)b * KCC + kc0) * DD;
        __nv_bfloat16* ol = (proj ? g_Vfl : g_Kel) + ((size_t)b * KCC + kc0) * DD;
#pragma unroll
        for (int mf = 0; mf < 4; mf++) {
            const int kcl = mw * 64 + mf * 16 + g;
            const float bv0 = bias[kc0 + kcl];
            const float bv8 = bias[kc0 + kcl + 8];
#pragma unroll
            for (int nf = 0; nf < 2; nf++) {
                const int d0 = nw * 16 + nf * 8 + 2 * q;
                float v0 = acc[bb][mf][nf][0] + bv0, v1 = acc[bb][mf][nf][1] + bv0;
                float v2 = acc[bb][mf][nf][2] + bv8, v3 = acc[bb][mf][nf][3] + bv8;
                *reinterpret_cast<uint32_t*>(&oh[(size_t)kcl * DD + d0]) = packbf(v0, v1);
                *reinterpret_cast<uint32_t*>(&oh[(size_t)(kcl + 8) * DD + d0]) = packbf(v2, v3);
                *reinterpret_cast<uint32_t*>(&ol[(size_t)kcl * DD + d0]) =
                    packbf(bfres(v0), bfres(v1));
                *reinterpret_cast<uint32_t*>(&ol[(size_t)(kcl + 8) * DD + d0]) =
                    packbf(bfres(v2), bfres(v3));
            }
        }
    }
}

// ---------------------------------------------------------------------------
// attn: tensor-core fused attention, rows 0..255 per batch only.
// Grid (4, B). Block 128 (4 warps x 16 rows).
// ---------------------------------------------------------------------------
__global__ __launch_bounds__(128) void attn_kernel(
    const float* __restrict__ Qf, float* __restrict__ out)
{
    extern __shared__ char sm[];
    const uint32_t smb = smem_u32(sm);
    const uint32_t KEH = 0, KEL = 32768, VFH = 65536, VFL = 98304,
                   QH = 131072, QL = 139264;

    const int tid = threadIdx.x, lane = tid & 31, warp = tid >> 5;
    const int b = blockIdx.y;
    const int s0 = blockIdx.x * 64;
    const int g = lane >> 2, q = lane & 3;
    const int lr = lane & 15, lcb = (lane >> 4) * 16;

    {
        const __nv_bfloat16* keh = g_Keh + (size_t)b * KCC * DD;
        const __nv_bfloat16* kel = g_Kel + (size_t)b * KCC * DD;
        const __nv_bfloat16* vfh = g_Vfh + (size_t)b * KCC * DD;
        const __nv_bfloat16* vfl = g_Vfl + (size_t)b * KCC * DD;
#pragma unroll
        for (int idx = tid; idx < 2048; idx += 128) {
            int row = idx >> 3, seg = idx & 7;
            size_t so = (size_t)row * DD + seg * 8;
            uint32_t bo = SW128((uint32_t)(row * 128 + seg * 16));
            cp16(smb + KEH + bo, keh + so);
            cp16(smb + KEL + bo, kel + so);
            cp16(smb + VFH + bo, vfh + so);
            cp16(smb + VFL + bo, vfl + so);
        }
        cp_commit();
    }
    {
        const float* qb = Qf + ((size_t)b * SS + s0) * DD;
#pragma unroll
        for (int idx = tid; idx < 512; idx += 128) {
            int row = idx >> 3, seg = idx & 7;
            const float* qp = qb + (size_t)row * DD + seg * 8;
            float4 v0 = *reinterpret_cast<const float4*>(qp);
            float4 v1 = *reinterpret_cast<const float4*>(qp + 4);
            uint32_t bo = SW128((uint32_t)(row * 128 + seg * 16));
            uint4 h, l;
            h.x = packbf(v0.x, v0.y); h.y = packbf(v0.z, v0.w);
            h.z = packbf(v1.x, v1.y); h.w = packbf(v1.z, v1.w);
            l.x = packbf(bfres(v0.x), bfres(v0.y));
            l.y = packbf(bfres(v0.z), bfres(v0.w));
            l.z = packbf(bfres(v1.x), bfres(v1.y));
            l.w = packbf(bfres(v1.z), bfres(v1.w));
            *reinterpret_cast<uint4*>(sm + QH + bo) = h;
            *reinterpret_cast<uint4*>(sm + QL + bo) = l;
        }
        cp_wait<0>();
        __syncthreads();
    }

    const int j0 = blockIdx.x * 4 + warp;

    float acc[32][4];
#pragma unroll
    for (int nf = 0; nf < 32; nf++)
#pragma unroll
        for (int i = 0; i < 4; i++) acc[nf][i] = 0.f;

#pragma unroll
    for (int kk = 0; kk < 4; kk++) {
        uint32_t qh[4], ql[4];
        uint32_t offA = SW128((uint32_t)((warp * 16 + lr) * 128 + kk * 32 + lcb));
        ldm_x4(qh, smb + QH + offA);
        ldm_x4(ql, smb + QL + offA);
#pragma unroll
        for (int j = 0; j < 16; j++) {
            if (j >= j0) {
                uint32_t off = SW128((uint32_t)((j * 16 + lr) * 128 + kk * 32 + lcb));
                uint32_t bh[4], bl[4];
                ldm_x4(bh, smb + KEH + off);
                ldm_x4(bl, smb + KEL + off);
                mma_bf16(acc[2 * j],     qh, bh[0], bh[2]);
                mma_bf16(acc[2 * j],     ql, bh[0], bh[2]);
                mma_bf16(acc[2 * j],     qh, bl[0], bl[2]);
                mma_bf16(acc[2 * j + 1], qh, bh[1], bh[3]);
                mma_bf16(acc[2 * j + 1], ql, bh[1], bh[3]);
                mma_bf16(acc[2 * j + 1], qh, bl[1], bl[3]);
            }
        }
    }

    const int rowa = s0 + warp * 16 + g;
    const int rowb = rowa + 8;
    float mxa = -3.4e38f, mxb = -3.4e38f;
#pragma unroll
    for (int nf = 0; nf < 32; nf++) {
        const int kc = 8 * nf + 2 * q;
        acc[nf][0] = (kc     >= rowa) ? acc[nf][0] * 0.125f : -1e10f;
        acc[nf][1] = (kc + 1 >= rowa) ? acc[nf][1] * 0.125f : -1e10f;
        acc[nf][2] = (kc     >= rowb) ? acc[nf][2] * 0.125f : -1e10f;
        acc[nf][3] = (kc + 1 >= rowb) ? acc[nf][3] * 0.125f : -1e10f;
        mxa = fmaxf(mxa, fmaxf(acc[nf][0], acc[nf][1]));
        mxb = fmaxf(mxb, fmaxf(acc[nf][2], acc[nf][3]));
    }
#pragma unroll
    for (int o = 1; o <= 2; o <<= 1) {
        mxa = fmaxf(mxa, __shfl_xor_sync(0xffffffffu, mxa, o));
        mxb = fmaxf(mxb, __shfl_xor_sync(0xffffffffu, mxb, o));
    }
    float sa = 0.f, sb = 0.f;
#pragma unroll
    for (int nf = 0; nf < 32; nf++) {
        acc[nf][0] = __expf(acc[nf][0] - mxa);
        acc[nf][1] = __expf(acc[nf][1] - mxa);
        acc[nf][2] = __expf(acc[nf][2] - mxb);
        acc[nf][3] = __expf(acc[nf][3] - mxb);
        sa += acc[nf][0] + acc[nf][1];
        sb += acc[nf][2] + acc[nf][3];
    }
#pragma unroll
    for (int o = 1; o <= 2; o <<= 1) {
        sa += __shfl_xor_sync(0xffffffffu, sa, o);
        sb += __shfl_xor_sync(0xffffffffu, sb, o);
    }
    const float inva = 1.f / sa, invb = 1.f / sb;

    uint32_t pAh[32], pAl[32], pBh[32], pBl[32];
#pragma unroll
    for (int nf = 0; nf < 32; nf++) {
        float p0 = acc[nf][0] * inva, p1 = acc[nf][1] * inva;
        float p2 = acc[nf][2] * invb, p3 = acc[nf][3] * invb;
        pAh[nf] = packbf(p0, p1);
        pBh[nf] = packbf(p2, p3);
        pAl[nf] = packbf(bfres(p0), bfres(p1));
        pBl[nf] = packbf(bfres(p2), bfres(p3));
    }

    float acc2[8][4];
#pragma unroll
    for (int u = 0; u < 8; u++)
#pragma unroll
        for (int i = 0; i < 4; i++) acc2[u][i] = 0.f;

#pragma unroll
    for (int ks = 0; ks < 16; ks++) {
        if (ks >= j0) {
            uint32_t a_h[4] = {pAh[2 * ks], pBh[2 * ks], pAh[2 * ks + 1], pBh[2 * ks + 1]};
            uint32_t a_l[4] = {pAl[2 * ks], pBl[2 * ks], pAl[2 * ks + 1], pBl[2 * ks + 1]};
#pragma unroll
            for (int t = 0; t < 4; t++) {
                uint32_t off = SW128((uint32_t)((ks * 16 + lr) * 128 + t * 32 + lcb));
                uint32_t vh[4], vl[4];
                ldm_x4_t(vh, smb + VFH + off);
                ldm_x4_t(vl, smb + VFL + off);
                mma_bf16(acc2[2 * t],     a_h, vh[0], vh[1]);
                mma_bf16(acc2[2 * t],     a_l, vh[0], vh[1]);
                mma_bf16(acc2[2 * t],     a_h, vl[0], vl[1]);
                mma_bf16(acc2[2 * t + 1], a_h, vh[2], vh[3]);
                mma_bf16(acc2[2 * t + 1], a_l, vh[2], vh[3]);
                mma_bf16(acc2[2 * t + 1], a_h, vl[2], vl[3]);
            }
        }
    }

    float* ob = out + (size_t)b * SS * DD;
#pragma unroll
    for (int u = 0; u < 8; u++) {
        const int d0 = 8 * u + 2 * q;
        *reinterpret_cast<float2*>(&ob[(size_t)rowa * DD + d0]) =
            make_float2(acc2[u][0], acc2[u][1]);
        *reinterpret_cast<float2*>(&ob[(size_t)rowb * DD + d0]) =
            make_float2(acc2[u][2], acc2[u][3]);
    }
}

// ---------------------------------------------------------------------------
// bcast: out[b][i][:] = mean_k Vf[b][k][:] for i in [256, 4096).
// Grid (B, 24), block 256; 160 rows per block. Mean via vectorized uint4
// loads (8 bf16 each): thread (kq, dg) accumulates k = kq+32t, d = 8dg..8dg+7.
// ---------------------------------------------------------------------------
__global__ __launch_bounds__(256) void bcast_kernel(float* __restrict__ out)
{
    __shared__ float psum[32][64];
    __shared__ float meanv[64];
    const int b = blockIdx.x, part = blockIdx.y;
    const int tid = threadIdx.x;
    const int kq = tid >> 3, dg = tid & 7;

    const __nv_bfloat16* vh = g_Vfh + (size_t)b * KCC * DD;
    const __nv_bfloat16* vl = g_Vfl + (size_t)b * KCC * DD;

    float s[8];
#pragma unroll
    for (int j = 0; j < 8; j++) s[j] = 0.f;
#pragma unroll
    for (int t = 0; t < 8; t++) {
        const int k = kq + 32 * t;
        uint4 h = *reinterpret_cast<const uint4*>(vh + (size_t)k * DD + dg * 8);
        uint4 l = *reinterpret_cast<const uint4*>(vl + (size_t)k * DD + dg * 8);
        const uint32_t* hw = &h.x;
        const uint32_t* lw = &l.x;
#pragma unroll
        for (int w = 0; w < 4; w++) {
            __nv_bfloat162 hv = *reinterpret_cast<const __nv_bfloat162*>(&hw[w]);
            __nv_bfloat162 lv = *reinterpret_cast<const __nv_bfloat162*>(&lw[w]);
            s[2 * w]     += __bfloat162float(hv.x) + __bfloat162float(lv.x);
            s[2 * w + 1] += __bfloat162float(hv.y) + __bfloat162float(lv.y);
        }
    }
#pragma unroll
    for (int j = 0; j < 8; j++) psum[kq][dg * 8 + j] = s[j];
    __syncthreads();
    if (tid < 64) {
        float t = 0.f;
#pragma unroll
        for (int k = 0; k < 32; k++) t += psum[k][tid];
        meanv[tid] = t * (1.f / 256.f);
    }
    __syncthreads();

    const int c = tid & 15, rofs = tid >> 4;
    const float4 val = make_float4(meanv[c * 4], meanv[c * 4 + 1],
                                   meanv[c * 4 + 2], meanv[c * 4 + 3]);
    float4* ob = reinterpret_cast<float4*>(out + (size_t)b * SS * DD);
    const int r0 = KCC + part * 160;
#pragma unroll 5
    for (int r = r0 + rofs; r < r0 + 160; r += 16)
        ob[(size_t)r * 16 + c] = val;
}

// ---------------------------------------------------------------------------
// Harness entry. Inputs: Q, K, V, E_w, E_b, F_w, F_b. Output f32 [B,S,D].
// ---------------------------------------------------------------------------
extern "C" void kernel_launch(void* const* d_in, const int* in_sizes, int n_in,
                              void* d_out, int out_size)
{
    (void)in_sizes; (void)n_in; (void)out_size;
    const float* Q   = (const float*)d_in[0];
    const float* K   = (const float*)d_in[1];
    const float* V   = (const float*)d_in[2];
    const float* E_w = (const float*)d_in[3];
    const float* E_b = (const float*)d_in[4];
    const float* F_w = (const float*)d_in[5];
    const float* F_b = (const float*)d_in[6];
    float* out = (float*)d_out;

    const int proj_smem = 196608;   // 192 KB
    const int attn_smem = 147456;   // 144 KB
    cudaFuncSetAttribute(proj_mma_kernel,
                         cudaFuncAttributeMaxDynamicSharedMemorySize, proj_smem);
    cudaFuncSetAttribute(attn_kernel,
                         cudaFuncAttributeMaxDynamicSharedMemorySize, attn_smem);

    conv_w_kernel<<<dim3(1024, 2), 256>>>(E_w, F_w);
    proj_mma_kernel<<<dim3(2, BB / 2, 2), 256, proj_smem>>>(K, V, E_b, F_b);
    attn_kernel<<<dim3(4, BB), 128, attn_smem>>>(Q, out);
    bcast_kernel<<<dim3(BB, 24), 256>>>(out);
}

// round 9
// speedup vs baseline: 1.4168x; 1.4168x over previous
#include <cuda_runtime.h>
#include <cuda_bf16.h>
#include <cstdint>

#define BB 32
#define SS 4096
#define DD 64
#define KCC 256

// ------------------------- device global scratch ---------------------------
__device__ __nv_bfloat16 g_Wh[2 * KCC * SS];       // [proj][kc][s] hi
__device__ __nv_bfloat16 g_Wl[2 * KCC * SS];       // lo
__device__ __nv_bfloat16 g_Keh[BB * KCC * DD];     // [b][kc][d] hi  (= Ke^T)
__device__ __nv_bfloat16 g_Kel[BB * KCC * DD];     // lo
__device__ __nv_bfloat16 g_Vfh[BB * KCC * DD];     // [b][kc][d] hi
__device__ __nv_bfloat16 g_Vfl[BB * KCC * DD];     // lo

// ------------------------------ helpers ------------------------------------
__device__ __forceinline__ uint32_t smem_u32(const void* p) {
    uint32_t a;
    asm("{ .reg .u64 t; cvta.to.shared.u64 t, %1; cvt.u32.u64 %0, t; }"
        : "=r"(a) : "l"(p));
    return a;
}
#define SW128(x) ((x) ^ (((x) >> 3) & 0x70))

__device__ __forceinline__ void cp16(uint32_t dst, const void* src) {
    asm volatile("cp.async.cg.shared.global [%0], [%1], 16;"
                 :: "r"(dst), "l"(src) : "memory");
}
__device__ __forceinline__ void cp_commit() {
    asm volatile("cp.async.commit_group;" ::: "memory");
}
template <int N>
__device__ __forceinline__ void cp_wait() {
    asm volatile("cp.async.wait_group %0;" :: "n"(N) : "memory");
}
__device__ __forceinline__ void ldm_x4(uint32_t* r, uint32_t addr) {
    asm volatile("ldmatrix.sync.aligned.m8n8.x4.shared.b16 {%0,%1,%2,%3}, [%4];"
                 : "=r"(r[0]), "=r"(r[1]), "=r"(r[2]), "=r"(r[3]) : "r"(addr));
}
__device__ __forceinline__ void ldm_x4_t(uint32_t* r, uint32_t addr) {
    asm volatile("ldmatrix.sync.aligned.m8n8.x4.trans.shared.b16 {%0,%1,%2,%3}, [%4];"
                 : "=r"(r[0]), "=r"(r[1]), "=r"(r[2]), "=r"(r[3]) : "r"(addr));
}
__device__ __forceinline__ void mma_bf16(
    float* c, const uint32_t* a, uint32_t b0, uint32_t b1) {
    asm volatile(
        "mma.sync.aligned.m16n8k16.row.col.f32.bf16.bf16.f32 "
        "{%0,%1,%2,%3}, {%4,%5,%6,%7}, {%8,%9}, {%0,%1,%2,%3};"
        : "+f"(c[0]), "+f"(c[1]), "+f"(c[2]), "+f"(c[3])
        : "r"(a[0]), "r"(a[1]), "r"(a[2]), "r"(a[3]), "r"(b0), "r"(b1));
}
__device__ __forceinline__ uint32_t packbf(float lo, float hi) {
    uint32_t r;
    asm("cvt.rn.bf16x2.f32 %0, %1, %2;" : "=r"(r) : "f"(hi), "f"(lo));
    return r;
}
__device__ __forceinline__ float bfres(float v) {   // v - bf16(v)
    return v - __bfloat162float(__float2bfloat16(v));
}

// ---------------------------------------------------------------------------
// conv_w: E_w / F_w (fp32 [256][4096]) -> bf16 hi/lo, same layout.
// ---------------------------------------------------------------------------
__global__ __launch_bounds__(256) void conv_w_kernel(
    const float* __restrict__ Ew, const float* __restrict__ Fw)
{
    const int y = blockIdx.y;
    const float4* src = reinterpret_cast<const float4*>(y ? Fw : Ew);
    const int i = blockIdx.x * 256 + threadIdx.x;
    float4 v = src[i];
    __nv_bfloat16 h0 = __float2bfloat16(v.x), h1 = __float2bfloat16(v.y),
                  h2 = __float2bfloat16(v.z), h3 = __float2bfloat16(v.w);
    __nv_bfloat16 l0 = __float2bfloat16(v.x - __bfloat162float(h0));
    __nv_bfloat16 l1 = __float2bfloat16(v.y - __bfloat162float(h1));
    __nv_bfloat16 l2 = __float2bfloat16(v.z - __bfloat162float(h2));
    __nv_bfloat16 l3 = __float2bfloat16(v.w - __bfloat162float(h3));
    __nv_bfloat162* oh = reinterpret_cast<__nv_bfloat162*>(
        g_Wh + (size_t)y * KCC * SS) + 2 * i;
    __nv_bfloat162* ol = reinterpret_cast<__nv_bfloat162*>(
        g_Wl + (size_t)y * KCC * SS) + 2 * i;
    oh[0] = __halves2bfloat162(h0, h1);
    oh[1] = __halves2bfloat162(h2, h3);
    ol[0] = __halves2bfloat162(l0, l1);
    ol[1] = __halves2bfloat162(l2, l3);
}

// ---------------------------------------------------------------------------
// proj_mma: mma.sync bf16 3-split GEMM.
//   D[kc][d] = sum_s W[kc][s] * X[s][d]   (M=128 kc, N=64 d, K=4096 s)
// Grid (2, B, 2) = 128 CTAs. Block 256 (2 m-groups x 4 n-groups).
// W AND X(fp32) both via 4-stage cp.async; X converted smem->smem to bf16
// hi/lo (thread converts exactly the segments it itself cp.async'd, so the
// per-thread wait_group suffices -- no extra barrier on the convert path).
// SMEM: W 4x32KB @0 | Xf 4x16KB @131072 | Xb 2x16KB @196608 = 224 KB.
// ---------------------------------------------------------------------------
__global__ __launch_bounds__(256) void proj_mma_kernel(
    const float* __restrict__ Kf, const float* __restrict__ Vf,
    const float* __restrict__ E_b, const float* __restrict__ F_b)
{
    extern __shared__ char sm[];
    const uint32_t smb = smem_u32(sm);
    const int tid = threadIdx.x, wid = tid >> 5, lane = tid & 31;
    const int kc0 = blockIdx.x * 128, b = blockIdx.y, proj = blockIdx.z;
    const int mw = wid >> 2, nw = wid & 3;
    const int g = lane >> 2, q = lane & 3;

    const __nv_bfloat16* Wh = g_Wh + ((size_t)proj * KCC + kc0) * SS;
    const __nv_bfloat16* Wl = g_Wl + ((size_t)proj * KCC + kc0) * SS;
    const float* Xb = (proj ? Vf : Kf) + (size_t)b * SS * DD;

    float acc[4][2][4];
#pragma unroll
    for (int mf = 0; mf < 4; mf++)
#pragma unroll
        for (int nf = 0; nf < 2; nf++)
#pragma unroll
            for (int i = 0; i < 4; i++) acc[mf][nf][i] = 0.f;

    const int NC = SS / 64;   // 64 chunks

    // chunk loader: W (bf16 hi/lo, swizzled) + X (fp32, linear). One group.
    auto load_chunk = [&](int c) {
        const uint32_t wbuf = smb + (c & 3) * 32768;
#pragma unroll
        for (int idx = tid; idx < 1024; idx += 256) {
            int row = idx >> 3, s16 = idx & 7;
            size_t so = (size_t)row * SS + c * 64 + s16 * 8;
            uint32_t bo = SW128((uint32_t)(row * 128 + s16 * 16));
            cp16(wbuf + bo,         Wh + so);
            cp16(wbuf + 16384 + bo, Wl + so);
        }
        const uint32_t xfbuf = smb + 131072 + (c & 3) * 16384;
        const float* xsrc = Xb + (size_t)c * 64 * DD;   // contiguous 16KB
#pragma unroll
        for (int u = 0; u < 2; u++) {
            int seg = tid + u * 256;                     // segment = 32B
            cp16(xfbuf + seg * 32,      xsrc + seg * 8);
            cp16(xfbuf + seg * 32 + 16, xsrc + seg * 8 + 4);
        }
        cp_commit();
    };

    // convert X fp32 (linear) -> bf16 hi/lo (swizzled); own-thread data only
    auto convert_x = [&](int c) {
        const char* xf = sm + 131072 + (c & 3) * 16384;
        char* xbb = sm + 196608 + (c & 1) * 16384;
#pragma unroll
        for (int u = 0; u < 2; u++) {
            int seg = tid + u * 256;
            int row = seg >> 3, s16 = seg & 7;
            float4 v0 = *reinterpret_cast<const float4*>(xf + seg * 32);
            float4 v1 = *reinterpret_cast<const float4*>(xf + seg * 32 + 16);
            uint32_t bo = SW128((uint32_t)(row * 128 + s16 * 16));
            uint4 h, l;
            h.x = packbf(v0.x, v0.y); h.y = packbf(v0.z, v0.w);
            h.z = packbf(v1.x, v1.y); h.w = packbf(v1.z, v1.w);
            l.x = packbf(bfres(v0.x), bfres(v0.y));
            l.y = packbf(bfres(v0.z), bfres(v0.w));
            l.z = packbf(bfres(v1.x), bfres(v1.y));
            l.w = packbf(bfres(v1.z), bfres(v1.w));
            *reinterpret_cast<uint4*>(xbb + bo)        = h;
            *reinterpret_cast<uint4*>(xbb + 8192 + bo) = l;
        }
    };

    load_chunk(0); load_chunk(1); load_chunk(2);

    for (int c = 0; c < NC; c++) {
        if (c + 3 < NC) { load_chunk(c + 3); cp_wait<3>(); }
        else            { cp_wait<0>(); }

        convert_x(c);
        __syncthreads();   // W stage + Xb visible to all warps

        const uint32_t wbuf = smb + (c & 3) * 32768;
        const uint32_t Ah = wbuf, Al = wbuf + 16384;
        const uint32_t xs = smb + 196608 + (c & 1) * 16384;
        const uint32_t Bh = xs, Bl = xs + 8192;
        const int lr = lane & 15, lc = (lane >> 4) * 16;

#pragma unroll
        for (int kk = 0; kk < 4; kk++) {
            uint32_t bh[4], bl[4];
            {
                uint32_t off = SW128((uint32_t)(
                    (kk * 16 + lr) * 128 + nw * 32 + lc));
                ldm_x4_t(bh, Bh + off);
                ldm_x4_t(bl, Bl + off);
            }
#pragma unroll
            for (int mf = 0; mf < 4; mf++) {
                uint32_t ah[4], al[4];
                uint32_t off = SW128((uint32_t)(
                    (mw * 64 + mf * 16 + lr) * 128 + kk * 32 + lc));
                ldm_x4(ah, Ah + off);
                ldm_x4(al, Al + off);
#pragma unroll
                for (int nf = 0; nf < 2; nf++) {
                    mma_bf16(acc[mf][nf], ah, bh[2 * nf], bh[2 * nf + 1]);
                    mma_bf16(acc[mf][nf], al, bh[2 * nf], bh[2 * nf + 1]);
                    mma_bf16(acc[mf][nf], ah, bl[2 * nf], bl[2 * nf + 1]);
                }
            }
        }
        __syncthreads();   // all MMA(c) done before W/Xf stage reuse
    }

    // ---- epilogue: bias add, bf16 hi/lo split, store [b][kc][d] ----
    const float* bias = proj ? F_b : E_b;
    __nv_bfloat16* oh = (proj ? g_Vfh : g_Keh) + ((size_t)b * KCC + kc0) * DD;
    __nv_bfloat16* ol = (proj ? g_Vfl : g_Kel) + ((size_t)b * KCC + kc0) * DD;
#pragma unroll
    for (int mf = 0; mf < 4; mf++) {
        const int kcl = mw * 64 + mf * 16 + g;
        const float bv0 = bias[kc0 + kcl];
        const float bv8 = bias[kc0 + kcl + 8];
#pragma unroll
        for (int nf = 0; nf < 2; nf++) {
            const int d0 = nw * 16 + nf * 8 + 2 * q;
            float v0 = acc[mf][nf][0] + bv0, v1 = acc[mf][nf][1] + bv0;
            float v2 = acc[mf][nf][2] + bv8, v3 = acc[mf][nf][3] + bv8;
            *reinterpret_cast<uint32_t*>(&oh[(size_t)kcl * DD + d0]) = packbf(v0, v1);
            *reinterpret_cast<uint32_t*>(&oh[(size_t)(kcl + 8) * DD + d0]) = packbf(v2, v3);
            *reinterpret_cast<uint32_t*>(&ol[(size_t)kcl * DD + d0]) =
                packbf(bfres(v0), bfres(v1));
            *reinterpret_cast<uint32_t*>(&ol[(size_t)(kcl + 8) * DD + d0]) =
                packbf(bfres(v2), bfres(v3));
        }
    }
}

// ---------------------------------------------------------------------------
// attn: tensor-core fused attention (rows 0..255) + fused broadcast of the
// fully-masked rows (256..4095 = column mean of Vf, exactly uniform softmax).
// Grid (4, B). Block 128 (4 warps x 16 rows). Each block also writes 960
// broadcast rows using the Vf tile already in smem (Q smem reused for the
// mean reduction).
// SMEM: Ke h/l 64K | Vf h/l 64K | Q h/l 16K = 144KB.
// ---------------------------------------------------------------------------
__global__ __launch_bounds__(128) void attn_kernel(
    const float* __restrict__ Qf, float* __restrict__ out)
{
    extern __shared__ char sm[];
    const uint32_t smb = smem_u32(sm);
    const uint32_t KEH = 0, KEL = 32768, VFH = 65536, VFL = 98304,
                   QH = 131072, QL = 139264;

    const int tid = threadIdx.x, lane = tid & 31, warp = tid >> 5;
    const int b = blockIdx.y;
    const int s0 = blockIdx.x * 64;
    const int g = lane >> 2, q = lane & 3;
    const int lr = lane & 15, lcb = (lane >> 4) * 16;

    {
        const __nv_bfloat16* keh = g_Keh + (size_t)b * KCC * DD;
        const __nv_bfloat16* kel = g_Kel + (size_t)b * KCC * DD;
        const __nv_bfloat16* vfh = g_Vfh + (size_t)b * KCC * DD;
        const __nv_bfloat16* vfl = g_Vfl + (size_t)b * KCC * DD;
#pragma unroll
        for (int idx = tid; idx < 2048; idx += 128) {
            int row = idx >> 3, seg = idx & 7;
            size_t so = (size_t)row * DD + seg * 8;
            uint32_t bo = SW128((uint32_t)(row * 128 + seg * 16));
            cp16(smb + KEH + bo, keh + so);
            cp16(smb + KEL + bo, kel + so);
            cp16(smb + VFH + bo, vfh + so);
            cp16(smb + VFL + bo, vfl + so);
        }
        cp_commit();
    }
    {
        const float* qb = Qf + ((size_t)b * SS + s0) * DD;
#pragma unroll
        for (int idx = tid; idx < 512; idx += 128) {
            int row = idx >> 3, seg = idx & 7;
            const float* qp = qb + (size_t)row * DD + seg * 8;
            float4 v0 = *reinterpret_cast<const float4*>(qp);
            float4 v1 = *reinterpret_cast<const float4*>(qp + 4);
            uint32_t bo = SW128((uint32_t)(row * 128 + seg * 16));
            uint4 h, l;
            h.x = packbf(v0.x, v0.y); h.y = packbf(v0.z, v0.w);
            h.z = packbf(v1.x, v1.y); h.w = packbf(v1.z, v1.w);
            l.x = packbf(bfres(v0.x), bfres(v0.y));
            l.y = packbf(bfres(v0.z), bfres(v0.w));
            l.z = packbf(bfres(v1.x), bfres(v1.y));
            l.w = packbf(bfres(v1.z), bfres(v1.w));
            *reinterpret_cast<uint4*>(sm + QH + bo) = h;
            *reinterpret_cast<uint4*>(sm + QL + bo) = l;
        }
        cp_wait<0>();
        __syncthreads();
    }

    const int j0 = blockIdx.x * 4 + warp;   // first possibly-unmasked kc tile

    float acc[32][4];
#pragma unroll
    for (int nf = 0; nf < 32; nf++)
#pragma unroll
        for (int i = 0; i < 4; i++) acc[nf][i] = 0.f;

#pragma unroll
    for (int kk = 0; kk < 4; kk++) {
        uint32_t qh[4], ql[4];
        uint32_t offA = SW128((uint32_t)((warp * 16 + lr) * 128 + kk * 32 + lcb));
        ldm_x4(qh, smb + QH + offA);
        ldm_x4(ql, smb + QL + offA);
#pragma unroll
        for (int j = 0; j < 16; j++) {
            if (j >= j0) {
                uint32_t off = SW128((uint32_t)((j * 16 + lr) * 128 + kk * 32 + lcb));
                uint32_t bh[4], bl[4];
                ldm_x4(bh, smb + KEH + off);
                ldm_x4(bl, smb + KEL + off);
                mma_bf16(acc[2 * j],     qh, bh[0], bh[2]);
                mma_bf16(acc[2 * j],     ql, bh[0], bh[2]);
                mma_bf16(acc[2 * j],     qh, bl[0], bl[2]);
                mma_bf16(acc[2 * j + 1], qh, bh[1], bh[3]);
                mma_bf16(acc[2 * j + 1], ql, bh[1], bh[3]);
                mma_bf16(acc[2 * j + 1], qh, bl[1], bl[3]);
            }
        }
    }

    const int rowa = s0 + warp * 16 + g;
    const int rowb = rowa + 8;
    float mxa = -3.4e38f, mxb = -3.4e38f;
#pragma unroll
    for (int nf = 0; nf < 32; nf++) {
        const int kc = 8 * nf + 2 * q;
        acc[nf][0] = (kc     >= rowa) ? acc[nf][0] * 0.125f : -1e10f;
        acc[nf][1] = (kc + 1 >= rowa) ? acc[nf][1] * 0.125f : -1e10f;
        acc[nf][2] = (kc     >= rowb) ? acc[nf][2] * 0.125f : -1e10f;
        acc[nf][3] = (kc + 1 >= rowb) ? acc[nf][3] * 0.125f : -1e10f;
        mxa = fmaxf(mxa, fmaxf(acc[nf][0], acc[nf][1]));
        mxb = fmaxf(mxb, fmaxf(acc[nf][2], acc[nf][3]));
    }
#pragma unroll
    for (int o = 1; o <= 2; o <<= 1) {
        mxa = fmaxf(mxa, __shfl_xor_sync(0xffffffffu, mxa, o));
        mxb = fmaxf(mxb, __shfl_xor_sync(0xffffffffu, mxb, o));
    }
    float sa = 0.f, sb = 0.f;
#pragma unroll
    for (int nf = 0; nf < 32; nf++) {
        acc[nf][0] = __expf(acc[nf][0] - mxa);
        acc[nf][1] = __expf(acc[nf][1] - mxa);
        acc[nf][2] = __expf(acc[nf][2] - mxb);
        acc[nf][3] = __expf(acc[nf][3] - mxb);
        sa += acc[nf][0] + acc[nf][1];
        sb += acc[nf][2] + acc[nf][3];
    }
#pragma unroll
    for (int o = 1; o <= 2; o <<= 1) {
        sa += __shfl_xor_sync(0xffffffffu, sa, o);
        sb += __shfl_xor_sync(0xffffffffu, sb, o);
    }
    const float inva = 1.f / sa, invb = 1.f / sb;

    uint32_t pAh[32], pAl[32], pBh[32], pBl[32];
#pragma unroll
    for (int nf = 0; nf < 32; nf++) {
        float p0 = acc[nf][0] * inva, p1 = acc[nf][1] * inva;
        float p2 = acc[nf][2] * invb, p3 = acc[nf][3] * invb;
        pAh[nf] = packbf(p0, p1);
        pBh[nf] = packbf(p2, p3);
        pAl[nf] = packbf(bfres(p0), bfres(p1));
        pBl[nf] = packbf(bfres(p2), bfres(p3));
    }

    float acc2[8][4];
#pragma unroll
    for (int u = 0; u < 8; u++)
#pragma unroll
        for (int i = 0; i < 4; i++) acc2[u][i] = 0.f;

#pragma unroll
    for (int ks = 0; ks < 16; ks++) {
        if (ks >= j0) {
            uint32_t a_h[4] = {pAh[2 * ks], pBh[2 * ks], pAh[2 * ks + 1], pBh[2 * ks + 1]};
            uint32_t a_l[4] = {pAl[2 * ks], pBl[2 * ks], pAl[2 * ks + 1], pBl[2 * ks + 1]};
#pragma unroll
            for (int t = 0; t < 4; t++) {
                uint32_t off = SW128((uint32_t)((ks * 16 + lr) * 128 + t * 32 + lcb));
                uint32_t vh[4], vl[4];
                ldm_x4_t(vh, smb + VFH + off);
                ldm_x4_t(vl, smb + VFL + off);
                mma_bf16(acc2[2 * t],     a_h, vh[0], vh[1]);
                mma_bf16(acc2[2 * t],     a_l, vh[0], vh[1]);
                mma_bf16(acc2[2 * t],     a_h, vl[0], vl[1]);
                mma_bf16(acc2[2 * t + 1], a_h, vh[2], vh[3]);
                mma_bf16(acc2[2 * t + 1], a_l, vh[2], vh[3]);
                mma_bf16(acc2[2 * t + 1], a_h, vl[2], vl[3]);
            }
        }
    }

    float* ob = out + (size_t)b * SS * DD;
#pragma unroll
    for (int u = 0; u < 8; u++) {
        const int d0 = 8 * u + 2 * q;
        *reinterpret_cast<float2*>(&ob[(size_t)rowa * DD + d0]) =
            make_float2(acc2[u][0], acc2[u][1]);
        *reinterpret_cast<float2*>(&ob[(size_t)rowb * DD + d0]) =
            make_float2(acc2[u][2], acc2[u][3]);
    }

    // ---- fused broadcast: rows >= KC get mean_k Vf[k][:] (exact uniform P).
    // Vf is already in smem; reuse the (dead) Q smem region for reduction.
    __syncthreads();
    {
        float* red = reinterpret_cast<float*>(sm + QH);          // [4][64]
        float* meanv = reinterpret_cast<float*>(sm + QH) + 256;  // [64]
        const int dp = tid & 31, kq = tid >> 5;                  // d-pair, k-quarter
        float m0 = 0.f, m1 = 0.f;
        for (int k = kq * 64; k < kq * 64 + 64; k++) {
            uint32_t off = SW128((uint32_t)(k * 128 + dp * 4));
            uint32_t hw = *reinterpret_cast<const uint32_t*>(sm + VFH + off);
            uint32_t lw = *reinterpret_cast<const uint32_t*>(sm + VFL + off);
            __nv_bfloat162 hv = *reinterpret_cast<__nv_bfloat162*>(&hw);
            __nv_bfloat162 lv = *reinterpret_cast<__nv_bfloat162*>(&lw);
            m0 += __bfloat162float(hv.x) + __bfloat162float(lv.x);
            m1 += __bfloat162float(hv.y) + __bfloat162float(lv.y);
        }
        red[kq * 64 + 2 * dp]     = m0;
        red[kq * 64 + 2 * dp + 1] = m1;
        __syncthreads();
        if (tid < 64)
            meanv[tid] = (red[tid] + red[64 + tid] + red[128 + tid] +
                          red[192 + tid]) * (1.f / 256.f);
        __syncthreads();

        const int ccol = tid & 15, rofs = tid >> 4;
        const float4 val = make_float4(meanv[ccol * 4], meanv[ccol * 4 + 1],
                                       meanv[ccol * 4 + 2], meanv[ccol * 4 + 3]);
        float4* obv = reinterpret_cast<float4*>(out + (size_t)b * SS * DD);
        const int r0b = KCC + blockIdx.x * 960;
#pragma unroll 4
        for (int r = r0b + rofs; r < r0b + 960; r += 8)
            obv[(size_t)r * 16 + ccol] = val;
    }
}

// ---------------------------------------------------------------------------
// Harness entry. Inputs: Q, K, V, E_w, E_b, F_w, F_b. Output f32 [B,S,D].
// ---------------------------------------------------------------------------
extern "C" void kernel_launch(void* const* d_in, const int* in_sizes, int n_in,
                              void* d_out, int out_size)
{
    (void)in_sizes; (void)n_in; (void)out_size;
    const float* Q   = (const float*)d_in[0];
    const float* K   = (const float*)d_in[1];
    const float* V   = (const float*)d_in[2];
    const float* E_w = (const float*)d_in[3];
    const float* E_b = (const float*)d_in[4];
    const float* F_w = (const float*)d_in[5];
    const float* F_b = (const float*)d_in[6];
    float* out = (float*)d_out;

    const int proj_smem = 229376;   // 224 KB (W 128K + Xf 64K + Xb 32K)
    const int attn_smem = 147456;   // 144 KB
    cudaFuncSetAttribute(proj_mma_kernel,
                         cudaFuncAttributeMaxDynamicSharedMemorySize, proj_smem);
    cudaFuncSetAttribute(attn_kernel,
                         cudaFuncAttributeMaxDynamicSharedMemorySize, attn_smem);

    conv_w_kernel<<<dim3(1024, 2), 256>>>(E_w, F_w);
    proj_mma_kernel<<<dim3(2, BB, 2), 256, proj_smem>>>(K, V, E_b, F_b);
    attn_kernel<<<dim3(4, BB), 128, attn_smem>>>(Q, out);
}

// round 10
// speedup vs baseline: 1.7431x; 1.2303x over previous
#include <cuda_runtime.h>
#include <cuda_bf16.h>
#include <cuda_fp16.h>
#include <cstdint>

#define BB 32
#define SS 4096
#define DD 64
#define KCC 256

// ------------------------- device global scratch ---------------------------
__device__ __half g_Wh[2 * KCC * SS];              // [proj][kc][s] fp16 hi
__device__ __half g_Wl[2 * KCC * SS];              // fp16 lo (W - Wh)
__device__ __nv_bfloat16 g_Keh[BB * KCC * DD];     // [b][kc][d] bf16 hi (= Ke^T)
__device__ __nv_bfloat16 g_Kel[BB * KCC * DD];     // lo
__device__ __nv_bfloat16 g_Vfh[BB * KCC * DD];     // [b][kc][d] bf16 hi
__device__ __nv_bfloat16 g_Vfl[BB * KCC * DD];     // lo

// ------------------------------ helpers ------------------------------------
__device__ __forceinline__ uint32_t smem_u32(const void* p) {
    uint32_t a;
    asm("{ .reg .u64 t; cvta.to.shared.u64 t, %1; cvt.u32.u64 %0, t; }"
        : "=r"(a) : "l"(p));
    return a;
}
#define SW128(x) ((x) ^ (((x) >> 3) & 0x70))

__device__ __forceinline__ void cp16(uint32_t dst, const void* src) {
    asm volatile("cp.async.cg.shared.global [%0], [%1], 16;"
                 :: "r"(dst), "l"(src) : "memory");
}
__device__ __forceinline__ void cp_commit() {
    asm volatile("cp.async.commit_group;" ::: "memory");
}
template <int N>
__device__ __forceinline__ void cp_wait() {
    asm volatile("cp.async.wait_group %0;" :: "n"(N) : "memory");
}
__device__ __forceinline__ void ldm_x4(uint32_t* r, uint32_t addr) {
    asm volatile("ldmatrix.sync.aligned.m8n8.x4.shared.b16 {%0,%1,%2,%3}, [%4];"
                 : "=r"(r[0]), "=r"(r[1]), "=r"(r[2]), "=r"(r[3]) : "r"(addr));
}
__device__ __forceinline__ void ldm_x4_t(uint32_t* r, uint32_t addr) {
    asm volatile("ldmatrix.sync.aligned.m8n8.x4.trans.shared.b16 {%0,%1,%2,%3}, [%4];"
                 : "=r"(r[0]), "=r"(r[1]), "=r"(r[2]), "=r"(r[3]) : "r"(addr));
}
__device__ __forceinline__ void mma_bf16(
    float* c, const uint32_t* a, uint32_t b0, uint32_t b1) {
    asm volatile(
        "mma.sync.aligned.m16n8k16.row.col.f32.bf16.bf16.f32 "
        "{%0,%1,%2,%3}, {%4,%5,%6,%7}, {%8,%9}, {%0,%1,%2,%3};"
        : "+f"(c[0]), "+f"(c[1]), "+f"(c[2]), "+f"(c[3])
        : "r"(a[0]), "r"(a[1]), "r"(a[2]), "r"(a[3]), "r"(b0), "r"(b1));
}
__device__ __forceinline__ void mma_f16(
    float* c, const uint32_t* a, uint32_t b0, uint32_t b1) {
    asm volatile(
        "mma.sync.aligned.m16n8k16.row.col.f32.f16.f16.f32 "
        "{%0,%1,%2,%3}, {%4,%5,%6,%7}, {%8,%9}, {%0,%1,%2,%3};"
        : "+f"(c[0]), "+f"(c[1]), "+f"(c[2]), "+f"(c[3])
        : "r"(a[0]), "r"(a[1]), "r"(a[2]), "r"(a[3]), "r"(b0), "r"(b1));
}
__device__ __forceinline__ uint32_t packbf(float lo, float hi) {
    uint32_t r;
    asm("cvt.rn.bf16x2.f32 %0, %1, %2;" : "=r"(r) : "f"(hi), "f"(lo));
    return r;
}
__device__ __forceinline__ uint32_t packhf(float lo, float hi) {
    uint32_t r;
    asm("cvt.rn.f16x2.f32 %0, %1, %2;" : "=r"(r) : "f"(hi), "f"(lo));
    return r;
}
__device__ __forceinline__ float bfres(float v) {   // v - bf16(v)
    return v - __bfloat162float(__float2bfloat16(v));
}

// ---------------------------------------------------------------------------
// conv_w: E_w / F_w (fp32 [256][4096]) -> fp16 hi/lo, same layout.
// ---------------------------------------------------------------------------
__global__ __launch_bounds__(256) void conv_w_kernel(
    const float* __restrict__ Ew, const float* __restrict__ Fw)
{
    const int y = blockIdx.y;
    const float4* src = reinterpret_cast<const float4*>(y ? Fw : Ew);
    const int i = blockIdx.x * 256 + threadIdx.x;
    float4 v = src[i];
    __half h0 = __float2half(v.x), h1 = __float2half(v.y),
           h2 = __float2half(v.z), h3 = __float2half(v.w);
    __half l0 = __float2half(v.x - __half2float(h0));
    __half l1 = __float2half(v.y - __half2float(h1));
    __half l2 = __float2half(v.z - __half2float(h2));
    __half l3 = __float2half(v.w - __half2float(h3));
    __half2* oh = reinterpret_cast<__half2*>(g_Wh + (size_t)y * KCC * SS) + 2 * i;
    __half2* ol = reinterpret_cast<__half2*>(g_Wl + (size_t)y * KCC * SS) + 2 * i;
    oh[0] = __halves2half2(h0, h1);
    oh[1] = __halves2half2(h2, h3);
    ol[0] = __halves2half2(l0, l1);
    ol[1] = __halves2half2(l2, l3);
}

// ---------------------------------------------------------------------------
// proj_mma: mma.sync fp16 2-term split GEMM.
//   D[kc][d] = sum_s W[kc][s] * X[s][d]   (M=128 kc, N=64 d, K=4096 s)
//   D = Wh*Xh + Wl*Xh  (fp16 hi/lo W exact to 2^-22; uncorrected X rounding
//   gives ~2.8e-4 rms, well under the 1e-3 budget).
// Grid (2, B, 2) = 128 CTAs. Block 256 (2 m-groups x 4 n-groups).
// W (fp16 hi/lo) and X (fp32) both via 4-stage cp.async; X converted
// smem->smem to fp16 hi only (own-thread segments; wait_group suffices).
// SMEM: W 4x32KB @0 | Xf 4x16KB @131072 | Xh 2x8KB @196608 = 208 KB.
// ---------------------------------------------------------------------------
__global__ __launch_bounds__(256) void proj_mma_kernel(
    const float* __restrict__ Kf, const float* __restrict__ Vf,
    const float* __restrict__ E_b, const float* __restrict__ F_b)
{
    extern __shared__ char sm[];
    const uint32_t smb = smem_u32(sm);
    const int tid = threadIdx.x, wid = tid >> 5, lane = tid & 31;
    const int kc0 = blockIdx.x * 128, b = blockIdx.y, proj = blockIdx.z;
    const int mw = wid >> 2, nw = wid & 3;
    const int g = lane >> 2, q = lane & 3;

    const __half* Wh = g_Wh + ((size_t)proj * KCC + kc0) * SS;
    const __half* Wl = g_Wl + ((size_t)proj * KCC + kc0) * SS;
    const float* Xb = (proj ? Vf : Kf) + (size_t)b * SS * DD;

    float acc[4][2][4];
#pragma unroll
    for (int mf = 0; mf < 4; mf++)
#pragma unroll
        for (int nf = 0; nf < 2; nf++)
#pragma unroll
            for (int i = 0; i < 4; i++) acc[mf][nf][i] = 0.f;

    const int NC = SS / 64;   // 64 chunks

    auto load_chunk = [&](int c) {
        const uint32_t wbuf = smb + (c & 3) * 32768;
#pragma unroll
        for (int idx = tid; idx < 1024; idx += 256) {
            int row = idx >> 3, s16 = idx & 7;
            size_t so = (size_t)row * SS + c * 64 + s16 * 8;
            uint32_t bo = SW128((uint32_t)(row * 128 + s16 * 16));
            cp16(wbuf + bo,         Wh + so);
            cp16(wbuf + 16384 + bo, Wl + so);
        }
        const uint32_t xfbuf = smb + 131072 + (c & 3) * 16384;
        const float* xsrc = Xb + (size_t)c * 64 * DD;   // contiguous 16KB
#pragma unroll
        for (int u = 0; u < 2; u++) {
            int seg = tid + u * 256;                     // 32B segments
            cp16(xfbuf + seg * 32,      xsrc + seg * 8);
            cp16(xfbuf + seg * 32 + 16, xsrc + seg * 8 + 4);
        }
        cp_commit();
    };

    // X fp32 (linear) -> fp16 hi (swizzled); own-thread segments only
    auto convert_x = [&](int c) {
        const char* xf = sm + 131072 + (c & 3) * 16384;
        char* xbb = sm + 196608 + (c & 1) * 8192;
#pragma unroll
        for (int u = 0; u < 2; u++) {
            int seg = tid + u * 256;
            int row = seg >> 3, s16 = seg & 7;
            float4 v0 = *reinterpret_cast<const float4*>(xf + seg * 32);
            float4 v1 = *reinterpret_cast<const float4*>(xf + seg * 32 + 16);
            uint32_t bo = SW128((uint32_t)(row * 128 + s16 * 16));
            uint4 h;
            h.x = packhf(v0.x, v0.y); h.y = packhf(v0.z, v0.w);
            h.z = packhf(v1.x, v1.y); h.w = packhf(v1.z, v1.w);
            *reinterpret_cast<uint4*>(xbb + bo) = h;
        }
    };

    load_chunk(0); load_chunk(1); load_chunk(2);

    for (int c = 0; c < NC; c++) {
        if (c + 3 < NC) { load_chunk(c + 3); cp_wait<3>(); }
        else            { cp_wait<0>(); }

        convert_x(c);
        __syncthreads();   // W stage + Xh visible to all warps

        const uint32_t wbuf = smb + (c & 3) * 32768;
        const uint32_t Ah = wbuf, Al = wbuf + 16384;
        const uint32_t Bh = smb + 196608 + (c & 1) * 8192;
        const int lr = lane & 15, lc = (lane >> 4) * 16;

#pragma unroll
        for (int kk = 0; kk < 4; kk++) {
            uint32_t bh[4];
            {
                uint32_t off = SW128((uint32_t)(
                    (kk * 16 + lr) * 128 + nw * 32 + lc));
                ldm_x4_t(bh, Bh + off);
            }
#pragma unroll
            for (int mf = 0; mf < 4; mf++) {
                uint32_t ah[4], al[4];
                uint32_t off = SW128((uint32_t)(
                    (mw * 64 + mf * 16 + lr) * 128 + kk * 32 + lc));
                ldm_x4(ah, Ah + off);
                ldm_x4(al, Al + off);
#pragma unroll
                for (int nf = 0; nf < 2; nf++) {
                    mma_f16(acc[mf][nf], ah, bh[2 * nf], bh[2 * nf + 1]);
                    mma_f16(acc[mf][nf], al, bh[2 * nf], bh[2 * nf + 1]);
                }
            }
        }
        __syncthreads();   // all MMA(c) done before stage reuse
    }

    // ---- epilogue: bias add, bf16 hi/lo split, store [b][kc][d] ----
    const float* bias = proj ? F_b : E_b;
    __nv_bfloat16* oh = (proj ? g_Vfh : g_Keh) + ((size_t)b * KCC + kc0) * DD;
    __nv_bfloat16* ol = (proj ? g_Vfl : g_Kel) + ((size_t)b * KCC + kc0) * DD;
#pragma unroll
    for (int mf = 0; mf < 4; mf++) {
        const int kcl = mw * 64 + mf * 16 + g;
        const float bv0 = bias[kc0 + kcl];
        const float bv8 = bias[kc0 + kcl + 8];
#pragma unroll
        for (int nf = 0; nf < 2; nf++) {
            const int d0 = nw * 16 + nf * 8 + 2 * q;
            float v0 = acc[mf][nf][0] + bv0, v1 = acc[mf][nf][1] + bv0;
            float v2 = acc[mf][nf][2] + bv8, v3 = acc[mf][nf][3] + bv8;
            *reinterpret_cast<uint32_t*>(&oh[(size_t)kcl * DD + d0]) = packbf(v0, v1);
            *reinterpret_cast<uint32_t*>(&oh[(size_t)(kcl + 8) * DD + d0]) = packbf(v2, v3);
            *reinterpret_cast<uint32_t*>(&ol[(size_t)kcl * DD + d0]) =
                packbf(bfres(v0), bfres(v1));
            *reinterpret_cast<uint32_t*>(&ol[(size_t)(kcl + 8) * DD + d0]) =
                packbf(bfres(v2), bfres(v3));
        }
    }
}

// ---------------------------------------------------------------------------
// attn: tensor-core fused attention (rows 0..255) + fused broadcast of the
// fully-masked rows (256..4095 = column mean of Vf, exactly uniform softmax).
// Grid (4, B). Block 128 (4 warps x 16 rows).
// SMEM: Ke h/l 64K | Vf h/l 64K | Q h/l 16K = 144KB.
// ---------------------------------------------------------------------------
__global__ __launch_bounds__(128) void attn_kernel(
    const float* __restrict__ Qf, float* __restrict__ out)
{
    extern __shared__ char sm[];
    const uint32_t smb = smem_u32(sm);
    const uint32_t KEH = 0, KEL = 32768, VFH = 65536, VFL = 98304,
                   QH = 131072, QL = 139264;

    const int tid = threadIdx.x, lane = tid & 31, warp = tid >> 5;
    const int b = blockIdx.y;
    const int s0 = blockIdx.x * 64;
    const int g = lane >> 2, q = lane & 3;
    const int lr = lane & 15, lcb = (lane >> 4) * 16;

    {
        const __nv_bfloat16* keh = g_Keh + (size_t)b * KCC * DD;
        const __nv_bfloat16* kel = g_Kel + (size_t)b * KCC * DD;
        const __nv_bfloat16* vfh = g_Vfh + (size_t)b * KCC * DD;
        const __nv_bfloat16* vfl = g_Vfl + (size_t)b * KCC * DD;
#pragma unroll
        for (int idx = tid; idx < 2048; idx += 128) {
            int row = idx >> 3, seg = idx & 7;
            size_t so = (size_t)row * DD + seg * 8;
            uint32_t bo = SW128((uint32_t)(row * 128 + seg * 16));
            cp16(smb + KEH + bo, keh + so);
            cp16(smb + KEL + bo, kel + so);
            cp16(smb + VFH + bo, vfh + so);
            cp16(smb + VFL + bo, vfl + so);
        }
        cp_commit();
    }
    {
        const float* qb = Qf + ((size_t)b * SS + s0) * DD;
#pragma unroll
        for (int idx = tid; idx < 512; idx += 128) {
            int row = idx >> 3, seg = idx & 7;
            const float* qp = qb + (size_t)row * DD + seg * 8;
            float4 v0 = *reinterpret_cast<const float4*>(qp);
            float4 v1 = *reinterpret_cast<const float4*>(qp + 4);
            uint32_t bo = SW128((uint32_t)(row * 128 + seg * 16));
            uint4 h, l;
            h.x = packbf(v0.x, v0.y); h.y = packbf(v0.z, v0.w);
            h.z = packbf(v1.x, v1.y); h.w = packbf(v1.z, v1.w);
            l.x = packbf(bfres(v0.x), bfres(v0.y));
            l.y = packbf(bfres(v0.z), bfres(v0.w));
            l.z = packbf(bfres(v1.x), bfres(v1.y));
            l.w = packbf(bfres(v1.z), bfres(v1.w));
            *reinterpret_cast<uint4*>(sm + QH + bo) = h;
            *reinterpret_cast<uint4*>(sm + QL + bo) = l;
        }
        cp_wait<0>();
        __syncthreads();
    }

    const int j0 = blockIdx.x * 4 + warp;   // first possibly-unmasked kc tile

    float acc[32][4];
#pragma unroll
    for (int nf = 0; nf < 32; nf++)
#pragma unroll
        for (int i = 0; i < 4; i++) acc[nf][i] = 0.f;

#pragma unroll
    for (int kk = 0; kk < 4; kk++) {
        uint32_t qh[4], ql[4];
        uint32_t offA = SW128((uint32_t)((warp * 16 + lr) * 128 + kk * 32 + lcb));
        ldm_x4(qh, smb + QH + offA);
        ldm_x4(ql, smb + QL + offA);
#pragma unroll
        for (int j = 0; j < 16; j++) {
            if (j >= j0) {
                uint32_t off = SW128((uint32_t)((j * 16 + lr) * 128 + kk * 32 + lcb));
                uint32_t bh[4], bl[4];
                ldm_x4(bh, smb + KEH + off);
                ldm_x4(bl, smb + KEL + off);
                mma_bf16(acc[2 * j],     qh, bh[0], bh[2]);
                mma_bf16(acc[2 * j],     ql, bh[0], bh[2]);
                mma_bf16(acc[2 * j],     qh, bl[0], bl[2]);
                mma_bf16(acc[2 * j + 1], qh, bh[1], bh[3]);
                mma_bf16(acc[2 * j + 1], ql, bh[1], bh[3]);
                mma_bf16(acc[2 * j + 1], qh, bl[1], bl[3]);
            }
        }
    }

    const int rowa = s0 + warp * 16 + g;
    const int rowb = rowa + 8;
    float mxa = -3.4e38f, mxb = -3.4e38f;
#pragma unroll
    for (int nf = 0; nf < 32; nf++) {
        const int kc = 8 * nf + 2 * q;
        acc[nf][0] = (kc     >= rowa) ? acc[nf][0] * 0.125f : -1e10f;
        acc[nf][1] = (kc + 1 >= rowa) ? acc[nf][1] * 0.125f : -1e10f;
        acc[nf][2] = (kc     >= rowb) ? acc[nf][2] * 0.125f : -1e10f;
        acc[nf][3] = (kc + 1 >= rowb) ? acc[nf][3] * 0.125f : -1e10f;
        mxa = fmaxf(mxa, fmaxf(acc[nf][0], acc[nf][1]));
        mxb = fmaxf(mxb, fmaxf(acc[nf][2], acc[nf][3]));
    }
#pragma unroll
    for (int o = 1; o <= 2; o <<= 1) {
        mxa = fmaxf(mxa, __shfl_xor_sync(0xffffffffu, mxa, o));
        mxb = fmaxf(mxb, __shfl_xor_sync(0xffffffffu, mxb, o));
    }
    float sa = 0.f, sb = 0.f;
#pragma unroll
    for (int nf = 0; nf < 32; nf++) {
        acc[nf][0] = __expf(acc[nf][0] - mxa);
        acc[nf][1] = __expf(acc[nf][1] - mxa);
        acc[nf][2] = __expf(acc[nf][2] - mxb);
        acc[nf][3] = __expf(acc[nf][3] - mxb);
        sa += acc[nf][0] + acc[nf][1];
        sb += acc[nf][2] + acc[nf][3];
    }
#pragma unroll
    for (int o = 1; o <= 2; o <<= 1) {
        sa += __shfl_xor_sync(0xffffffffu, sa, o);
        sb += __shfl_xor_sync(0xffffffffu, sb, o);
    }
    const float inva = 1.f / sa, invb = 1.f / sb;

    uint32_t pAh[32], pAl[32], pBh[32], pBl[32];
#pragma unroll
    for (int nf = 0; nf < 32; nf++) {
        float p0 = acc[nf][0] * inva, p1 = acc[nf][1] * inva;
        float p2 = acc[nf][2] * invb, p3 = acc[nf][3] * invb;
        pAh[nf] = packbf(p0, p1);
        pBh[nf] = packbf(p2, p3);
        pAl[nf] = packbf(bfres(p0), bfres(p1));
        pBl[nf] = packbf(bfres(p2), bfres(p3));
    }

    float acc2[8][4];
#pragma unroll
    for (int u = 0; u < 8; u++)
#pragma unroll
        for (int i = 0; i < 4; i++) acc2[u][i] = 0.f;

#pragma unroll
    for (int ks = 0; ks < 16; ks++) {
        if (ks >= j0) {
            uint32_t a_h[4] = {pAh[2 * ks], pBh[2 * ks], pAh[2 * ks + 1], pBh[2 * ks + 1]};
            uint32_t a_l[4] = {pAl[2 * ks], pBl[2 * ks], pAl[2 * ks + 1], pBl[2 * ks + 1]};
#pragma unroll
            for (int t = 0; t < 4; t++) {
                uint32_t off = SW128((uint32_t)((ks * 16 + lr) * 128 + t * 32 + lcb));
                uint32_t vh[4], vl[4];
                ldm_x4_t(vh, smb + VFH + off);
                ldm_x4_t(vl, smb + VFL + off);
                mma_bf16(acc2[2 * t],     a_h, vh[0], vh[1]);
                mma_bf16(acc2[2 * t],     a_l, vh[0], vh[1]);
                mma_bf16(acc2[2 * t],     a_h, vl[0], vl[1]);
                mma_bf16(acc2[2 * t + 1], a_h, vh[2], vh[3]);
                mma_bf16(acc2[2 * t + 1], a_l, vh[2], vh[3]);
                mma_bf16(acc2[2 * t + 1], a_h, vl[2], vl[3]);
            }
        }
    }

    float* ob = out + (size_t)b * SS * DD;
#pragma unroll
    for (int u = 0; u < 8; u++) {
        const int d0 = 8 * u + 2 * q;
        *reinterpret_cast<float2*>(&ob[(size_t)rowa * DD + d0]) =
            make_float2(acc2[u][0], acc2[u][1]);
        *reinterpret_cast<float2*>(&ob[(size_t)rowb * DD + d0]) =
            make_float2(acc2[u][2], acc2[u][3]);
    }

    // ---- fused broadcast: rows >= KC get mean_k Vf[k][:] (exact uniform P).
    __syncthreads();
    {
        float* red = reinterpret_cast<float*>(sm + QH);          // [4][64]
        float* meanv = reinterpret_cast<float*>(sm + QH) + 256;  // [64]
        const int dp = tid & 31, kq = tid >> 5;
        float m0 = 0.f, m1 = 0.f;
        for (int k = kq * 64; k < kq * 64 + 64; k++) {
            uint32_t off = SW128((uint32_t)(k * 128 + dp * 4));
            uint32_t hw = *reinterpret_cast<const uint32_t*>(sm + VFH + off);
            uint32_t lw = *reinterpret_cast<const uint32_t*>(sm + VFL + off);
            __nv_bfloat162 hv = *reinterpret_cast<__nv_bfloat162*>(&hw);
            __nv_bfloat162 lv = *reinterpret_cast<__nv_bfloat162*>(&lw);
            m0 += __bfloat162float(hv.x) + __bfloat162float(lv.x);
            m1 += __bfloat162float(hv.y) + __bfloat162float(lv.y);
        }
        red[kq * 64 + 2 * dp]     = m0;
        red[kq * 64 + 2 * dp + 1] = m1;
        __syncthreads();
        if (tid < 64)
            meanv[tid] = (red[tid] + red[64 + tid] + red[128 + tid] +
                          red[192 + tid]) * (1.f / 256.f);
        __syncthreads();

        const int ccol = tid & 15, rofs = tid >> 4;
        const float4 val = make_float4(meanv[ccol * 4], meanv[ccol * 4 + 1],
                                       meanv[ccol * 4 + 2], meanv[ccol * 4 + 3]);
        float4* obv = reinterpret_cast<float4*>(out + (size_t)b * SS * DD);
        const int r0b = KCC + blockIdx.x * 960;
#pragma unroll 4
        for (int r = r0b + rofs; r < r0b + 960; r += 8)
            obv[(size_t)r * 16 + ccol] = val;
    }
}

// ---------------------------------------------------------------------------
// Harness entry. Inputs: Q, K, V, E_w, E_b, F_w, F_b. Output f32 [B,S,D].
// ---------------------------------------------------------------------------
extern "C" void kernel_launch(void* const* d_in, const int* in_sizes, int n_in,
                              void* d_out, int out_size)
{
    (void)in_sizes; (void)n_in; (void)out_size;
    const float* Q   = (const float*)d_in[0];
    const float* K   = (const float*)d_in[1];
    const float* V   = (const float*)d_in[2];
    const float* E_w = (const float*)d_in[3];
    const float* E_b = (const float*)d_in[4];
    const float* F_w = (const float*)d_in[5];
    const float* F_b = (const float*)d_in[6];
    float* out = (float*)d_out;

    const int proj_smem = 212992;   // 208 KB (W 128K + Xf 64K + Xh 16K)
    const int attn_smem = 147456;   // 144 KB
    cudaFuncSetAttribute(proj_mma_kernel,
                         cudaFuncAttributeMaxDynamicSharedMemorySize, proj_smem);
    cudaFuncSetAttribute(attn_kernel,
                         cudaFuncAttributeMaxDynamicSharedMemorySize, attn_smem);

    conv_w_kernel<<<dim3(1024, 2), 256>>>(E_w, F_w);
    proj_mma_kernel<<<dim3(2, BB, 2), 256, proj_smem>>>(K, V, E_b, F_b);
    attn_kernel<<<dim3(4, BB), 128, attn_smem>>>(Q, out);
}

// round 11
// speedup vs baseline: 2.1990x; 1.2615x over previous
#include <cuda_runtime.h>
#include <cuda_bf16.h>
#include <cuda_fp16.h>
#include <cstdint>

#define BB 32
#define SS 4096
#define DD 64
#define KCC 256

// ------------------------- device global scratch ---------------------------
__device__ __half g_Wh[2 * KCC * SS];              // [proj][kc][s] fp16
__device__ __nv_bfloat16 g_Keh[BB * KCC * DD];     // [b][kc][d] bf16 hi (= Ke^T)
__device__ __nv_bfloat16 g_Kel[BB * KCC * DD];     // lo
__device__ __nv_bfloat16 g_Vfh[BB * KCC * DD];     // [b][kc][d] bf16 hi
__device__ __nv_bfloat16 g_Vfl[BB * KCC * DD];     // lo

// ------------------------------ helpers ------------------------------------
__device__ __forceinline__ uint32_t smem_u32(const void* p) {
    uint32_t a;
    asm("{ .reg .u64 t; cvta.to.shared.u64 t, %1; cvt.u32.u64 %0, t; }"
        : "=r"(a) : "l"(p));
    return a;
}
#define SW128(x) ((x) ^ (((x) >> 3) & 0x70))

__device__ __forceinline__ void cp16(uint32_t dst, const void* src) {
    asm volatile("cp.async.cg.shared.global [%0], [%1], 16;"
                 :: "r"(dst), "l"(src) : "memory");
}
__device__ __forceinline__ void cp_commit() {
    asm volatile("cp.async.commit_group;" ::: "memory");
}
template <int N>
__device__ __forceinline__ void cp_wait() {
    asm volatile("cp.async.wait_group %0;" :: "n"(N) : "memory");
}
__device__ __forceinline__ void ldm_x4(uint32_t* r, uint32_t addr) {
    asm volatile("ldmatrix.sync.aligned.m8n8.x4.shared.b16 {%0,%1,%2,%3}, [%4];"
                 : "=r"(r[0]), "=r"(r[1]), "=r"(r[2]), "=r"(r[3]) : "r"(addr));
}
__device__ __forceinline__ void ldm_x4_t(uint32_t* r, uint32_t addr) {
    asm volatile("ldmatrix.sync.aligned.m8n8.x4.trans.shared.b16 {%0,%1,%2,%3}, [%4];"
                 : "=r"(r[0]), "=r"(r[1]), "=r"(r[2]), "=r"(r[3]) : "r"(addr));
}
__device__ __forceinline__ void mma_bf16(
    float* c, const uint32_t* a, uint32_t b0, uint32_t b1) {
    asm volatile(
        "mma.sync.aligned.m16n8k16.row.col.f32.bf16.bf16.f32 "
        "{%0,%1,%2,%3}, {%4,%5,%6,%7}, {%8,%9}, {%0,%1,%2,%3};"
        : "+f"(c[0]), "+f"(c[1]), "+f"(c[2]), "+f"(c[3])
        : "r"(a[0]), "r"(a[1]), "r"(a[2]), "r"(a[3]), "r"(b0), "r"(b1));
}
__device__ __forceinline__ void mma_f16(
    float* c, const uint32_t* a, uint32_t b0, uint32_t b1) {
    asm volatile(
        "mma.sync.aligned.m16n8k16.row.col.f32.f16.f16.f32 "
        "{%0,%1,%2,%3}, {%4,%5,%6,%7}, {%8,%9}, {%0,%1,%2,%3};"
        : "+f"(c[0]), "+f"(c[1]), "+f"(c[2]), "+f"(c[3])
        : "r"(a[0]), "r"(a[1]), "r"(a[2]), "r"(a[3]), "r"(b0), "r"(b1));
}
__device__ __forceinline__ uint32_t packbf(float lo, float hi) {
    uint32_t r;
    asm("cvt.rn.bf16x2.f32 %0, %1, %2;" : "=r"(r) : "f"(hi), "f"(lo));
    return r;
}
__device__ __forceinline__ uint32_t packhf(float lo, float hi) {
    uint32_t r;
    asm("cvt.rn.f16x2.f32 %0, %1, %2;" : "=r"(r) : "f"(hi), "f"(lo));
    return r;
}
__device__ __forceinline__ float bfres(float v) {   // v - bf16(v)
    return v - __bfloat162float(__float2bfloat16(v));
}

// ---------------------------------------------------------------------------
// conv_w: E_w / F_w (fp32 [256][4096]) -> fp16, same layout. Grid (1024, 2).
// ---------------------------------------------------------------------------
__global__ __launch_bounds__(256) void conv_w_kernel(
    const float* __restrict__ Ew, const float* __restrict__ Fw)
{
    const int y = blockIdx.y;
    const float4* src = reinterpret_cast<const float4*>(y ? Fw : Ew);
    const int i = blockIdx.x * 256 + threadIdx.x;
    float4 v = src[i];
    __half2* oh = reinterpret_cast<__half2*>(g_Wh + (size_t)y * KCC * SS) + 2 * i;
    oh[0] = __halves2half2(__float2half(v.x), __float2half(v.y));
    oh[1] = __halves2half2(__float2half(v.z), __float2half(v.w));
}

// ---------------------------------------------------------------------------
// proj_mma: mma.sync fp16 single-term GEMM.
//   D[kc][d] = sum_s Wh[kc][s] * Xh[s][d]   (M=128 kc, N=64 d, K=4096 s)
//   fp16 roundings of W and X each ~2.3e-4 rms (calibrated R10) -> ~3.3e-4
//   total, 3x under the 1e-3 budget.
// Grid (2, B, 2) = 128 CTAs. Block 256 (2 m-groups x 4 n-groups).
// W (fp16) and X (fp32) via 4-stage cp.async; X converted smem->smem to
// fp16 (own-thread segments; per-thread wait_group covers the convert).
// SMEM: W 4x16KB @0 | Xf 4x16KB @65536 | Xh 2x8KB @131072 = 144 KB.
// ---------------------------------------------------------------------------
__global__ __launch_bounds__(256) void proj_mma_kernel(
    const float* __restrict__ Kf, const float* __restrict__ Vf,
    const float* __restrict__ E_b, const float* __restrict__ F_b)
{
    extern __shared__ char sm[];
    const uint32_t smb = smem_u32(sm);
    const int tid = threadIdx.x, wid = tid >> 5, lane = tid & 31;
    const int kc0 = blockIdx.x * 128, b = blockIdx.y, proj = blockIdx.z;
    const int mw = wid >> 2, nw = wid & 3;
    const int g = lane >> 2, q = lane & 3;

    const __half* Wh = g_Wh + ((size_t)proj * KCC + kc0) * SS;
    const float* Xb = (proj ? Vf : Kf) + (size_t)b * SS * DD;

    float acc[4][2][4];
#pragma unroll
    for (int mf = 0; mf < 4; mf++)
#pragma unroll
        for (int nf = 0; nf < 2; nf++)
#pragma unroll
            for (int i = 0; i < 4; i++) acc[mf][nf][i] = 0.f;

    const int NC = SS / 64;   // 64 chunks

    auto load_chunk = [&](int c) {
        const uint32_t wbuf = smb + (c & 3) * 16384;
#pragma unroll
        for (int idx = tid; idx < 1024; idx += 256) {
            int row = idx >> 3, s16 = idx & 7;
            size_t so = (size_t)row * SS + c * 64 + s16 * 8;
            uint32_t bo = SW128((uint32_t)(row * 128 + s16 * 16));
            cp16(wbuf + bo, Wh + so);
        }
        const uint32_t xfbuf = smb + 65536 + (c & 3) * 16384;
        const float* xsrc = Xb + (size_t)c * 64 * DD;   // contiguous 16KB
#pragma unroll
        for (int u = 0; u < 2; u++) {
            int seg = tid + u * 256;                     // 32B segments
            cp16(xfbuf + seg * 32,      xsrc + seg * 8);
            cp16(xfbuf + seg * 32 + 16, xsrc + seg * 8 + 4);
        }
        cp_commit();
    };

    // X fp32 (linear) -> fp16 (swizzled); own-thread segments only
    auto convert_x = [&](int c) {
        const char* xf = sm + 65536 + (c & 3) * 16384;
        char* xbb = sm + 131072 + (c & 1) * 8192;
#pragma unroll
        for (int u = 0; u < 2; u++) {
            int seg = tid + u * 256;
            int row = seg >> 3, s16 = seg & 7;
            float4 v0 = *reinterpret_cast<const float4*>(xf + seg * 32);
            float4 v1 = *reinterpret_cast<const float4*>(xf + seg * 32 + 16);
            uint32_t bo = SW128((uint32_t)(row * 128 + s16 * 16));
            uint4 h;
            h.x = packhf(v0.x, v0.y); h.y = packhf(v0.z, v0.w);
            h.z = packhf(v1.x, v1.y); h.w = packhf(v1.z, v1.w);
            *reinterpret_cast<uint4*>(xbb + bo) = h;
        }
    };

    load_chunk(0); load_chunk(1); load_chunk(2);

    for (int c = 0; c < NC; c++) {
        if (c + 3 < NC) { load_chunk(c + 3); cp_wait<3>(); }
        else            { cp_wait<0>(); }

        convert_x(c);
        __syncthreads();   // W stage + Xh visible to all warps

        const uint32_t Ah = smb + (c & 3) * 16384;
        const uint32_t Bh = smb + 131072 + (c & 1) * 8192;
        const int lr = lane & 15, lc = (lane >> 4) * 16;

#pragma unroll
        for (int kk = 0; kk < 4; kk++) {
            uint32_t bh[4];
            {
                uint32_t off = SW128((uint32_t)(
                    (kk * 16 + lr) * 128 + nw * 32 + lc));
                ldm_x4_t(bh, Bh + off);
            }
#pragma unroll
            for (int mf = 0; mf < 4; mf++) {
                uint32_t ah[4];
                uint32_t off = SW128((uint32_t)(
                    (mw * 64 + mf * 16 + lr) * 128 + kk * 32 + lc));
                ldm_x4(ah, Ah + off);
#pragma unroll
                for (int nf = 0; nf < 2; nf++)
                    mma_f16(acc[mf][nf], ah, bh[2 * nf], bh[2 * nf + 1]);
            }
        }
        __syncthreads();   // all MMA(c) done before stage reuse
    }

    // ---- epilogue: bias add, bf16 hi/lo split, store [b][kc][d] ----
    const float* bias = proj ? F_b : E_b;
    __nv_bfloat16* oh = (proj ? g_Vfh : g_Keh) + ((size_t)b * KCC + kc0) * DD;
    __nv_bfloat16* ol = (proj ? g_Vfl : g_Kel) + ((size_t)b * KCC + kc0) * DD;
#pragma unroll
    for (int mf = 0; mf < 4; mf++) {
        const int kcl = mw * 64 + mf * 16 + g;
        const float bv0 = bias[kc0 + kcl];
        const float bv8 = bias[kc0 + kcl + 8];
#pragma unroll
        for (int nf = 0; nf < 2; nf++) {
            const int d0 = nw * 16 + nf * 8 + 2 * q;
            float v0 = acc[mf][nf][0] + bv0, v1 = acc[mf][nf][1] + bv0;
            float v2 = acc[mf][nf][2] + bv8, v3 = acc[mf][nf][3] + bv8;
            *reinterpret_cast<uint32_t*>(&oh[(size_t)kcl * DD + d0]) = packbf(v0, v1);
            *reinterpret_cast<uint32_t*>(&oh[(size_t)(kcl + 8) * DD + d0]) = packbf(v2, v3);
            *reinterpret_cast<uint32_t*>(&ol[(size_t)kcl * DD + d0]) =
                packbf(bfres(v0), bfres(v1));
            *reinterpret_cast<uint32_t*>(&ol[(size_t)(kcl + 8) * DD + d0]) =
                packbf(bfres(v2), bfres(v3));
        }
    }
}

// ---------------------------------------------------------------------------
// attn: tensor-core fused attention (rows 0..255) + fused broadcast of the
// fully-masked rows (256..4095 = column mean of Vf, exactly uniform softmax).
// Grid (4, B). Block 128 (4 warps x 16 rows).
// SMEM: Ke h/l 64K | Vf h/l 64K | Q h/l 16K = 144KB.
// ---------------------------------------------------------------------------
__global__ __launch_bounds__(128) void attn_kernel(
    const float* __restrict__ Qf, float* __restrict__ out)
{
    extern __shared__ char sm[];
    const uint32_t smb = smem_u32(sm);
    const uint32_t KEH = 0, KEL = 32768, VFH = 65536, VFL = 98304,
                   QH = 131072, QL = 139264;

    const int tid = threadIdx.x, lane = tid & 31, warp = tid >> 5;
    const int b = blockIdx.y;
    const int s0 = blockIdx.x * 64;
    const int g = lane >> 2, q = lane & 3;
    const int lr = lane & 15, lcb = (lane >> 4) * 16;

    {
        const __nv_bfloat16* keh = g_Keh + (size_t)b * KCC * DD;
        const __nv_bfloat16* kel = g_Kel + (size_t)b * KCC * DD;
        const __nv_bfloat16* vfh = g_Vfh + (size_t)b * KCC * DD;
        const __nv_bfloat16* vfl = g_Vfl + (size_t)b * KCC * DD;
#pragma unroll
        for (int idx = tid; idx < 2048; idx += 128) {
            int row = idx >> 3, seg = idx & 7;
            size_t so = (size_t)row * DD + seg * 8;
            uint32_t bo = SW128((uint32_t)(row * 128 + seg * 16));
            cp16(smb + KEH + bo, keh + so);
            cp16(smb + KEL + bo, kel + so);
            cp16(smb + VFH + bo, vfh + so);
            cp16(smb + VFL + bo, vfl + so);
        }
        cp_commit();
    }
    {
        const float* qb = Qf + ((size_t)b * SS + s0) * DD;
#pragma unroll
        for (int idx = tid; idx < 512; idx += 128) {
            int row = idx >> 3, seg = idx & 7;
            const float* qp = qb + (size_t)row * DD + seg * 8;
            float4 v0 = *reinterpret_cast<const float4*>(qp);
            float4 v1 = *reinterpret_cast<const float4*>(qp + 4);
            uint32_t bo = SW128((uint32_t)(row * 128 + seg * 16));
            uint4 h, l;
            h.x = packbf(v0.x, v0.y); h.y = packbf(v0.z, v0.w);
            h.z = packbf(v1.x, v1.y); h.w = packbf(v1.z, v1.w);
            l.x = packbf(bfres(v0.x), bfres(v0.y));
            l.y = packbf(bfres(v0.z), bfres(v0.w));
            l.z = packbf(bfres(v1.x), bfres(v1.y));
            l.w = packbf(bfres(v1.z), bfres(v1.w));
            *reinterpret_cast<uint4*>(sm + QH + bo) = h;
            *reinterpret_cast<uint4*>(sm + QL + bo) = l;
        }
        cp_wait<0>();
        __syncthreads();
    }

    const int j0 = blockIdx.x * 4 + warp;   // first possibly-unmasked kc tile

    float acc[32][4];
#pragma unroll
    for (int nf = 0; nf < 32; nf++)
#pragma unroll
        for (int i = 0; i < 4; i++) acc[nf][i] = 0.f;

#pragma unroll
    for (int kk = 0; kk < 4; kk++) {
        uint32_t qh[4], ql[4];
        uint32_t offA = SW128((uint32_t)((warp * 16 + lr) * 128 + kk * 32 + lcb));
        ldm_x4(qh, smb + QH + offA);
        ldm_x4(ql, smb + QL + offA);
#pragma unroll
        for (int j = 0; j < 16; j++) {
            if (j >= j0) {
                uint32_t off = SW128((uint32_t)((j * 16 + lr) * 128 + kk * 32 + lcb));
                uint32_t bh[4], bl[4];
                ldm_x4(bh, smb + KEH + off);
                ldm_x4(bl, smb + KEL + off);
                mma_bf16(acc[2 * j],     qh, bh[0], bh[2]);
                mma_bf16(acc[2 * j],     ql, bh[0], bh[2]);
                mma_bf16(acc[2 * j],     qh, bl[0], bl[2]);
                mma_bf16(acc[2 * j + 1], qh, bh[1], bh[3]);
                mma_bf16(acc[2 * j + 1], ql, bh[1], bh[3]);
                mma_bf16(acc[2 * j + 1], qh, bl[1], bl[3]);
            }
        }
    }

    const int rowa = s0 + warp * 16 + g;
    const int rowb = rowa + 8;
    float mxa = -3.4e38f, mxb = -3.4e38f;
#pragma unroll
    for (int nf = 0; nf < 32; nf++) {
        const int kc = 8 * nf + 2 * q;
        acc[nf][0] = (kc     >= rowa) ? acc[nf][0] * 0.125f : -1e10f;
        acc[nf][1] = (kc + 1 >= rowa) ? acc[nf][1] * 0.125f : -1e10f;
        acc[nf][2] = (kc     >= rowb) ? acc[nf][2] * 0.125f : -1e10f;
        acc[nf][3] = (kc + 1 >= rowb) ? acc[nf][3] * 0.125f : -1e10f;
        mxa = fmaxf(mxa, fmaxf(acc[nf][0], acc[nf][1]));
        mxb = fmaxf(mxb, fmaxf(acc[nf][2], acc[nf][3]));
    }
#pragma unroll
    for (int o = 1; o <= 2; o <<= 1) {
        mxa = fmaxf(mxa, __shfl_xor_sync(0xffffffffu, mxa, o));
        mxb = fmaxf(mxb, __shfl_xor_sync(0xffffffffu, mxb, o));
    }
    float sa = 0.f, sb = 0.f;
#pragma unroll
    for (int nf = 0; nf < 32; nf++) {
        acc[nf][0] = __expf(acc[nf][0] - mxa);
        acc[nf][1] = __expf(acc[nf][1] - mxa);
        acc[nf][2] = __expf(acc[nf][2] - mxb);
        acc[nf][3] = __expf(acc[nf][3] - mxb);
        sa += acc[nf][0] + acc[nf][1];
        sb += acc[nf][2] + acc[nf][3];
    }
#pragma unroll
    for (int o = 1; o <= 2; o <<= 1) {
        sa += __shfl_xor_sync(0xffffffffu, sa, o);
        sb += __shfl_xor_sync(0xffffffffu, sb, o);
    }
    const float inva = 1.f / sa, invb = 1.f / sb;

    uint32_t pAh[32], pAl[32], pBh[32], pBl[32];
#pragma unroll
    for (int nf = 0; nf < 32; nf++) {
        float p0 = acc[nf][0] * inva, p1 = acc[nf][1] * inva;
        float p2 = acc[nf][2] * invb, p3 = acc[nf][3] * invb;
        pAh[nf] = packbf(p0, p1);
        pBh[nf] = packbf(p2, p3);
        pAl[nf] = packbf(bfres(p0), bfres(p1));
        pBl[nf] = packbf(bfres(p2), bfres(p3));
    }

    float acc2[8][4];
#pragma unroll
    for (int u = 0; u < 8; u++)
#pragma unroll
        for (int i = 0; i < 4; i++) acc2[u][i] = 0.f;

#pragma unroll
    for (int ks = 0; ks < 16; ks++) {
        if (ks >= j0) {
            uint32_t a_h[4] = {pAh[2 * ks], pBh[2 * ks], pAh[2 * ks + 1], pBh[2 * ks + 1]};
            uint32_t a_l[4] = {pAl[2 * ks], pBl[2 * ks], pAl[2 * ks + 1], pBl[2 * ks + 1]};
#pragma unroll
            for (int t = 0; t < 4; t++) {
                uint32_t off = SW128((uint32_t)((ks * 16 + lr) * 128 + t * 32 + lcb));
                uint32_t vh[4], vl[4];
                ldm_x4_t(vh, smb + VFH + off);
                ldm_x4_t(vl, smb + VFL + off);
                mma_bf16(acc2[2 * t],     a_h, vh[0], vh[1]);
                mma_bf16(acc2[2 * t],     a_l, vh[0], vh[1]);
                mma_bf16(acc2[2 * t],     a_h, vl[0], vl[1]);
                mma_bf16(acc2[2 * t + 1], a_h, vh[2], vh[3]);
                mma_bf16(acc2[2 * t + 1], a_l, vh[2], vh[3]);
                mma_bf16(acc2[2 * t + 1], a_h, vl[2], vl[3]);
            }
        }
    }

    float* ob = out + (size_t)b * SS * DD;
#pragma unroll
    for (int u = 0; u < 8; u++) {
        const int d0 = 8 * u + 2 * q;
        *reinterpret_cast<float2*>(&ob[(size_t)rowa * DD + d0]) =
            make_float2(acc2[u][0], acc2[u][1]);
        *reinterpret_cast<float2*>(&ob[(size_t)rowb * DD + d0]) =
            make_float2(acc2[u][2], acc2[u][3]);
    }

    // ---- fused broadcast: rows >= KC get mean_k Vf[k][:] (exact uniform P).
    __syncthreads();
    {
        float* red = reinterpret_cast<float*>(sm + QH);          // [4][64]
        float* meanv = reinterpret_cast<float*>(sm + QH) + 256;  // [64]
        const int dp = tid & 31, kq = tid >> 5;
        float m0 = 0.f, m1 = 0.f;
        for (int k = kq * 64; k < kq * 64 + 64; k++) {
            uint32_t off = SW128((uint32_t)(k * 128 + dp * 4));
            uint32_t hw = *reinterpret_cast<const uint32_t*>(sm + VFH + off);
            uint32_t lw = *reinterpret_cast<const uint32_t*>(sm + VFL + off);
            __nv_bfloat162 hv = *reinterpret_cast<__nv_bfloat162*>(&hw);
            __nv_bfloat162 lv = *reinterpret_cast<__nv_bfloat162*>(&lw);
            m0 += __bfloat162float(hv.x) + __bfloat162float(lv.x);
            m1 += __bfloat162float(hv.y) + __bfloat162float(lv.y);
        }
        red[kq * 64 + 2 * dp]     = m0;
        red[kq * 64 + 2 * dp + 1] = m1;
        __syncthreads();
        if (tid < 64)
            meanv[tid] = (red[tid] + red[64 + tid] + red[128 + tid] +
                          red[192 + tid]) * (1.f / 256.f);
        __syncthreads();

        const int ccol = tid & 15, rofs = tid >> 4;
        const float4 val = make_float4(meanv[ccol * 4], meanv[ccol * 4 + 1],
                                       meanv[ccol * 4 + 2], meanv[ccol * 4 + 3]);
        float4* obv = reinterpret_cast<float4*>(out + (size_t)b * SS * DD);
        const int r0b = KCC + blockIdx.x * 960;
#pragma unroll 4
        for (int r = r0b + rofs; r < r0b + 960; r += 8)
            obv[(size_t)r * 16 + ccol] = val;
    }
}

// ---------------------------------------------------------------------------
// Harness entry. Inputs: Q, K, V, E_w, E_b, F_w, F_b. Output f32 [B,S,D].
// ---------------------------------------------------------------------------
extern "C" void kernel_launch(void* const* d_in, const int* in_sizes, int n_in,
                              void* d_out, int out_size)
{
    (void)in_sizes; (void)n_in; (void)out_size;
    const float* Q   = (const float*)d_in[0];
    const float* K   = (const float*)d_in[1];
    const float* V   = (const float*)d_in[2];
    const float* E_w = (const float*)d_in[3];
    const float* E_b = (const float*)d_in[4];
    const float* F_w = (const float*)d_in[5];
    const float* F_b = (const float*)d_in[6];
    float* out = (float*)d_out;

    const int proj_smem = 147456;   // 144 KB (W 64K + Xf 64K + Xh 16K)
    const int attn_smem = 147456;   // 144 KB
    cudaFuncSetAttribute(proj_mma_kernel,
                         cudaFuncAttributeMaxDynamicSharedMemorySize, proj_smem);
    cudaFuncSetAttribute(attn_kernel,
                         cudaFuncAttributeMaxDynamicSharedMemorySize, attn_smem);

    conv_w_kernel<<<dim3(1024, 2), 256>>>(E_w, F_w);
    proj_mma_kernel<<<dim3(2, BB, 2), 256, proj_smem>>>(K, V, E_b, F_b);
    attn_kernel<<<dim3(4, BB), 128, attn_smem>>>(Q, out);
}

// round 12
// speedup vs baseline: 2.3820x; 1.0832x over previous
#include <cuda_runtime.h>
#include <cuda_bf16.h>
#include <cuda_fp16.h>
#include <cstdint>

#define BB 32
#define SS 4096
#define DD 64
#define KCC 256

// ------------------------- device global scratch ---------------------------
__device__ __half g_Wh[2 * KCC * SS];        // [proj][kc][s] fp16
__device__ float  g_acc[2 * BB * KCC * DD];  // [proj][b][kc][d] fp32 partial sums

// ------------------------------ helpers ------------------------------------
__device__ __forceinline__ uint32_t smem_u32(const void* p) {
    uint32_t a;
    asm("{ .reg .u64 t; cvta.to.shared.u64 t, %1; cvt.u32.u64 %0, t; }"
        : "=r"(a) : "l"(p));
    return a;
}
#define SW128(x) ((x) ^ (((x) >> 3) & 0x70))

__device__ __forceinline__ void cp16(uint32_t dst, const void* src) {
    asm volatile("cp.async.cg.shared.global [%0], [%1], 16;"
                 :: "r"(dst), "l"(src) : "memory");
}
__device__ __forceinline__ void cp_commit() {
    asm volatile("cp.async.commit_group;" ::: "memory");
}
template <int N>
__device__ __forceinline__ void cp_wait() {
    asm volatile("cp.async.wait_group %0;" :: "n"(N) : "memory");
}
__device__ __forceinline__ void ldm_x4(uint32_t* r, uint32_t addr) {
    asm volatile("ldmatrix.sync.aligned.m8n8.x4.shared.b16 {%0,%1,%2,%3}, [%4];"
                 : "=r"(r[0]), "=r"(r[1]), "=r"(r[2]), "=r"(r[3]) : "r"(addr));
}
__device__ __forceinline__ void ldm_x4_t(uint32_t* r, uint32_t addr) {
    asm volatile("ldmatrix.sync.aligned.m8n8.x4.trans.shared.b16 {%0,%1,%2,%3}, [%4];"
                 : "=r"(r[0]), "=r"(r[1]), "=r"(r[2]), "=r"(r[3]) : "r"(addr));
}
__device__ __forceinline__ void mma_bf16(
    float* c, const uint32_t* a, uint32_t b0, uint32_t b1) {
    asm volatile(
        "mma.sync.aligned.m16n8k16.row.col.f32.bf16.bf16.f32 "
        "{%0,%1,%2,%3}, {%4,%5,%6,%7}, {%8,%9}, {%0,%1,%2,%3};"
        : "+f"(c[0]), "+f"(c[1]), "+f"(c[2]), "+f"(c[3])
        : "r"(a[0]), "r"(a[1]), "r"(a[2]), "r"(a[3]), "r"(b0), "r"(b1));
}
__device__ __forceinline__ void mma_f16(
    float* c, const uint32_t* a, uint32_t b0, uint32_t b1) {
    asm volatile(
        "mma.sync.aligned.m16n8k16.row.col.f32.f16.f16.f32 "
        "{%0,%1,%2,%3}, {%4,%5,%6,%7}, {%8,%9}, {%0,%1,%2,%3};"
        : "+f"(c[0]), "+f"(c[1]), "+f"(c[2]), "+f"(c[3])
        : "r"(a[0]), "r"(a[1]), "r"(a[2]), "r"(a[3]), "r"(b0), "r"(b1));
}
__device__ __forceinline__ uint32_t packbf(float lo, float hi) {
    uint32_t r;
    asm("cvt.rn.bf16x2.f32 %0, %1, %2;" : "=r"(r) : "f"(hi), "f"(lo));
    return r;
}
__device__ __forceinline__ uint32_t packhf(float lo, float hi) {
    uint32_t r;
    asm("cvt.rn.f16x2.f32 %0, %1, %2;" : "=r"(r) : "f"(hi), "f"(lo));
    return r;
}
__device__ __forceinline__ float bfres(float v) {   // v - bf16(v)
    return v - __bfloat162float(__float2bfloat16(v));
}

// ---------------------------------------------------------------------------
// conv_w: E_w / F_w (fp32 [256][4096]) -> fp16, same layout. Grid (1024, 2).
// ---------------------------------------------------------------------------
__global__ __launch_bounds__(256) void conv_w_kernel(
    const float* __restrict__ Ew, const float* __restrict__ Fw)
{
    const int y = blockIdx.y;
    const float4* src = reinterpret_cast<const float4*>(y ? Fw : Ew);
    const int i = blockIdx.x * 256 + threadIdx.x;
    float4 v = src[i];
    __half2* oh = reinterpret_cast<__half2*>(g_Wh + (size_t)y * KCC * SS) + 2 * i;
    oh[0] = __halves2half2(__float2half(v.x), __float2half(v.y));
    oh[1] = __halves2half2(__float2half(v.z), __float2half(v.w));
}

// ---------------------------------------------------------------------------
// proj_mma: mma.sync fp16 GEMM, s-split to stream X from DRAM exactly once.
//   partial[kc][d] = sum_{s in half} Wh[kc][s] * Xh[s][d]
//   (M=256 kc full, N=64 d, K=2048 = half the s range per CTA)
// Grid (2 s-halves, B, 2 proj) = 128 CTAs. Block 256 (2 m x 4 n warp groups,
// warp tile M=128). Epilogue: scalar fp32 atomicAdd into g_acc (exactly two
// commutative contributions per element -> bitwise deterministic).
// SMEM: W 3x32KB @0 | Xf 3x16KB @98304 | Xh 2x8KB @147456 = 160 KB.
// ---------------------------------------------------------------------------
__global__ __launch_bounds__(256) void proj_mma_kernel(
    const float* __restrict__ Kf, const float* __restrict__ Vf)
{
    extern __shared__ char sm[];
    const uint32_t smb = smem_u32(sm);
    const int tid = threadIdx.x, wid = tid >> 5, lane = tid & 31;
    const int shalf = blockIdx.x, b = blockIdx.y, proj = blockIdx.z;
    const int mw = wid >> 2, nw = wid & 3;
    const int g = lane >> 2, q = lane & 3;

    const __half* Wh = g_Wh + (size_t)proj * KCC * SS;          // full 256 kc
    const float* Xb = (proj ? Vf : Kf) + (size_t)b * SS * DD;
    const int sbase = shalf * 2048;

    float acc[8][2][4];
#pragma unroll
    for (int mf = 0; mf < 8; mf++)
#pragma unroll
        for (int nf = 0; nf < 2; nf++)
#pragma unroll
            for (int i = 0; i < 4; i++) acc[mf][nf][i] = 0.f;

    const int NC = 2048 / 64;   // 32 chunks per CTA

    auto load_chunk = [&](int c) {
        const uint32_t wbuf = smb + (c % 3) * 32768;
#pragma unroll
        for (int idx = tid; idx < 2048; idx += 256) {           // W: 256 rows
            int row = idx >> 3, s16 = idx & 7;
            size_t so = (size_t)row * SS + sbase + c * 64 + s16 * 8;
            uint32_t bo = SW128((uint32_t)(row * 128 + s16 * 16));
            cp16(wbuf + bo, Wh + so);
        }
        const uint32_t xfbuf = smb + 98304 + (c % 3) * 16384;
        const float* xsrc = Xb + (size_t)(sbase + c * 64) * DD; // contiguous 16KB
#pragma unroll
        for (int u = 0; u < 2; u++) {
            int seg = tid + u * 256;                            // 32B segments
            cp16(xfbuf + seg * 32,      xsrc + seg * 8);
            cp16(xfbuf + seg * 32 + 16, xsrc + seg * 8 + 4);
        }
        cp_commit();
    };

    // X fp32 (linear) -> fp16 (swizzled); own-thread segments only
    auto convert_x = [&](int c) {
        const char* xf = sm + 98304 + (c % 3) * 16384;
        char* xbb = sm + 147456 + (c & 1) * 8192;
#pragma unroll
        for (int u = 0; u < 2; u++) {
            int seg = tid + u * 256;
            int row = seg >> 3, s16 = seg & 7;
            float4 v0 = *reinterpret_cast<const float4*>(xf + seg * 32);
            float4 v1 = *reinterpret_cast<const float4*>(xf + seg * 32 + 16);
            uint32_t bo = SW128((uint32_t)(row * 128 + s16 * 16));
            uint4 h;
            h.x = packhf(v0.x, v0.y); h.y = packhf(v0.z, v0.w);
            h.z = packhf(v1.x, v1.y); h.w = packhf(v1.z, v1.w);
            *reinterpret_cast<uint4*>(xbb + bo) = h;
        }
    };

    load_chunk(0); load_chunk(1);

    for (int c = 0; c < NC; c++) {
        if (c + 2 < NC) { load_chunk(c + 2); cp_wait<2>(); }
        else            { cp_wait<0>(); }

        convert_x(c);
        __syncthreads();   // W stage + Xh visible to all warps

        const uint32_t Ah = smb + (c % 3) * 32768;
        const uint32_t Bh = smb + 147456 + (c & 1) * 8192;
        const int lr = lane & 15, lc = (lane >> 4) * 16;

#pragma unroll
        for (int kk = 0; kk < 4; kk++) {
            uint32_t bh[4];
            {
                uint32_t off = SW128((uint32_t)(
                    (kk * 16 + lr) * 128 + nw * 32 + lc));
                ldm_x4_t(bh, Bh + off);
            }
#pragma unroll
            for (int mf = 0; mf < 8; mf++) {
                uint32_t ah[4];
                uint32_t off = SW128((uint32_t)(
                    (mw * 128 + mf * 16 + lr) * 128 + kk * 32 + lc));
                ldm_x4(ah, Ah + off);
#pragma unroll
                for (int nf = 0; nf < 2; nf++)
                    mma_f16(acc[mf][nf], ah, bh[2 * nf], bh[2 * nf + 1]);
            }
        }
        __syncthreads();   // all MMA(c) done before stage reuse
    }

    // ---- epilogue: atomic accumulate fp32 partials into g_acc ----
    float* out = g_acc + ((size_t)proj * BB + b) * KCC * DD;
#pragma unroll
    for (int mf = 0; mf < 8; mf++) {
        const int kcl = mw * 128 + mf * 16 + g;
#pragma unroll
        for (int nf = 0; nf < 2; nf++) {
            const int d0 = nw * 16 + nf * 8 + 2 * q;
            atomicAdd(&out[(size_t)kcl * DD + d0],           acc[mf][nf][0]);
            atomicAdd(&out[(size_t)kcl * DD + d0 + 1],       acc[mf][nf][1]);
            atomicAdd(&out[(size_t)(kcl + 8) * DD + d0],     acc[mf][nf][2]);
            atomicAdd(&out[(size_t)(kcl + 8) * DD + d0 + 1], acc[mf][nf][3]);
        }
    }
}

// ---------------------------------------------------------------------------
// attn: tensor-core fused attention (rows 0..255) + fused broadcast of the
// fully-masked rows (256..4095 = column mean of Vf, exactly uniform softmax).
// Loads Ke/Vf as fp32 from g_acc (adds bias) and splits to bf16 hi/lo in the
// loader. Grid (4, B). Block 128 (4 warps x 16 rows).
// SMEM: Ke h/l 64K | Vf h/l 64K | Q h/l 16K = 144KB.
// ---------------------------------------------------------------------------
__global__ __launch_bounds__(128) void attn_kernel(
    const float* __restrict__ Qf,
    const float* __restrict__ E_b, const float* __restrict__ F_b,
    float* __restrict__ out)
{
    extern __shared__ char sm[];
    const uint32_t smb = smem_u32(sm);
    const uint32_t KEH = 0, KEL = 32768, VFH = 65536, VFL = 98304,
                   QH = 131072, QL = 139264;

    const int tid = threadIdx.x, lane = tid & 31, warp = tid >> 5;
    const int b = blockIdx.y;
    const int s0 = blockIdx.x * 64;
    const int g = lane >> 2, q = lane & 3;
    const int lr = lane & 15, lcb = (lane >> 4) * 16;

    // ---- Ke / Vf: fp32 from g_acc (+ bias) -> bf16 hi/lo smem tiles ----
    {
        const float* keA = g_acc + (size_t)b * KCC * DD;                 // proj 0
        const float* vfA = g_acc + ((size_t)BB + b) * KCC * DD;          // proj 1
#pragma unroll
        for (int idx = tid; idx < 2048; idx += 128) {
            int row = idx >> 3, seg = idx & 7;
            uint32_t bo = SW128((uint32_t)(row * 128 + seg * 16));
            // Ke row
            {
                const float* p = keA + (size_t)row * DD + seg * 8;
                float bv = E_b[row];
                float4 v0 = *reinterpret_cast<const float4*>(p);
                float4 v1 = *reinterpret_cast<const float4*>(p + 4);
                v0.x += bv; v0.y += bv; v0.z += bv; v0.w += bv;
                v1.x += bv; v1.y += bv; v1.z += bv; v1.w += bv;
                uint4 h, l;
                h.x = packbf(v0.x, v0.y); h.y = packbf(v0.z, v0.w);
                h.z = packbf(v1.x, v1.y); h.w = packbf(v1.z, v1.w);
                l.x = packbf(bfres(v0.x), bfres(v0.y));
                l.y = packbf(bfres(v0.z), bfres(v0.w));
                l.z = packbf(bfres(v1.x), bfres(v1.y));
                l.w = packbf(bfres(v1.z), bfres(v1.w));
                *reinterpret_cast<uint4*>(sm + KEH + bo) = h;
                *reinterpret_cast<uint4*>(sm + KEL + bo) = l;
            }
            // Vf row
            {
                const float* p = vfA + (size_t)row * DD + seg * 8;
                float bv = F_b[row];
                float4 v0 = *reinterpret_cast<const float4*>(p);
                float4 v1 = *reinterpret_cast<const float4*>(p + 4);
                v0.x += bv; v0.y += bv; v0.z += bv; v0.w += bv;
                v1.x += bv; v1.y += bv; v1.z += bv; v1.w += bv;
                uint4 h, l;
                h.x = packbf(v0.x, v0.y); h.y = packbf(v0.z, v0.w);
                h.z = packbf(v1.x, v1.y); h.w = packbf(v1.z, v1.w);
                l.x = packbf(bfres(v0.x), bfres(v0.y));
                l.y = packbf(bfres(v0.z), bfres(v0.w));
                l.z = packbf(bfres(v1.x), bfres(v1.y));
                l.w = packbf(bfres(v1.z), bfres(v1.w));
                *reinterpret_cast<uint4*>(sm + VFH + bo) = h;
                *reinterpret_cast<uint4*>(sm + VFL + bo) = l;
            }
        }
    }
    // ---- Q: fp32 -> bf16 hi/lo smem ----
    {
        const float* qb = Qf + ((size_t)b * SS + s0) * DD;
#pragma unroll
        for (int idx = tid; idx < 512; idx += 128) {
            int row = idx >> 3, seg = idx & 7;
            const float* qp = qb + (size_t)row * DD + seg * 8;
            float4 v0 = *reinterpret_cast<const float4*>(qp);
            float4 v1 = *reinterpret_cast<const float4*>(qp + 4);
            uint32_t bo = SW128((uint32_t)(row * 128 + seg * 16));
            uint4 h, l;
            h.x = packbf(v0.x, v0.y); h.y = packbf(v0.z, v0.w);
            h.z = packbf(v1.x, v1.y); h.w = packbf(v1.z, v1.w);
            l.x = packbf(bfres(v0.x), bfres(v0.y));
            l.y = packbf(bfres(v0.z), bfres(v0.w));
            l.z = packbf(bfres(v1.x), bfres(v1.y));
            l.w = packbf(bfres(v1.z), bfres(v1.w));
            *reinterpret_cast<uint4*>(sm + QH + bo) = h;
            *reinterpret_cast<uint4*>(sm + QL + bo) = l;
        }
    }
    __syncthreads();

    const int j0 = blockIdx.x * 4 + warp;   // first possibly-unmasked kc tile

    float acc[32][4];
#pragma unroll
    for (int nf = 0; nf < 32; nf++)
#pragma unroll
        for (int i = 0; i < 4; i++) acc[nf][i] = 0.f;

#pragma unroll
    for (int kk = 0; kk < 4; kk++) {
        uint32_t qh[4], ql[4];
        uint32_t offA = SW128((uint32_t)((warp * 16 + lr) * 128 + kk * 32 + lcb));
        ldm_x4(qh, smb + QH + offA);
        ldm_x4(ql, smb + QL + offA);
#pragma unroll
        for (int j = 0; j < 16; j++) {
            if (j >= j0) {
                uint32_t off = SW128((uint32_t)((j * 16 + lr) * 128 + kk * 32 + lcb));
                uint32_t bh[4], bl[4];
                ldm_x4(bh, smb + KEH + off);
                ldm_x4(bl, smb + KEL + off);
                mma_bf16(acc[2 * j],     qh, bh[0], bh[2]);
                mma_bf16(acc[2 * j],     ql, bh[0], bh[2]);
                mma_bf16(acc[2 * j],     qh, bl[0], bl[2]);
                mma_bf16(acc[2 * j + 1], qh, bh[1], bh[3]);
                mma_bf16(acc[2 * j + 1], ql, bh[1], bh[3]);
                mma_bf16(acc[2 * j + 1], qh, bl[1], bl[3]);
            }
        }
    }

    const int rowa = s0 + warp * 16 + g;
    const int rowb = rowa + 8;
    float mxa = -3.4e38f, mxb = -3.4e38f;
#pragma unroll
    for (int nf = 0; nf < 32; nf++) {
        const int kc = 8 * nf + 2 * q;
        acc[nf][0] = (kc     >= rowa) ? acc[nf][0] * 0.125f : -1e10f;
        acc[nf][1] = (kc + 1 >= rowa) ? acc[nf][1] * 0.125f : -1e10f;
        acc[nf][2] = (kc     >= rowb) ? acc[nf][2] * 0.125f : -1e10f;
        acc[nf][3] = (kc + 1 >= rowb) ? acc[nf][3] * 0.125f : -1e10f;
        mxa = fmaxf(mxa, fmaxf(acc[nf][0], acc[nf][1]));
        mxb = fmaxf(mxb, fmaxf(acc[nf][2], acc[nf][3]));
    }
#pragma unroll
    for (int o = 1; o <= 2; o <<= 1) {
        mxa = fmaxf(mxa, __shfl_xor_sync(0xffffffffu, mxa, o));
        mxb = fmaxf(mxb, __shfl_xor_sync(0xffffffffu, mxb, o));
    }
    float sa = 0.f, sb = 0.f;
#pragma unroll
    for (int nf = 0; nf < 32; nf++) {
        acc[nf][0] = __expf(acc[nf][0] - mxa);
        acc[nf][1] = __expf(acc[nf][1] - mxa);
        acc[nf][2] = __expf(acc[nf][2] - mxb);
        acc[nf][3] = __expf(acc[nf][3] - mxb);
        sa += acc[nf][0] + acc[nf][1];
        sb += acc[nf][2] + acc[nf][3];
    }
#pragma unroll
    for (int o = 1; o <= 2; o <<= 1) {
        sa += __shfl_xor_sync(0xffffffffu, sa, o);
        sb += __shfl_xor_sync(0xffffffffu, sb, o);
    }
    const float inva = 1.f / sa, invb = 1.f / sb;

    uint32_t pAh[32], pAl[32], pBh[32], pBl[32];
#pragma unroll
    for (int nf = 0; nf < 32; nf++) {
        float p0 = acc[nf][0] * inva, p1 = acc[nf][1] * inva;
        float p2 = acc[nf][2] * invb, p3 = acc[nf][3] * invb;
        pAh[nf] = packbf(p0, p1);
        pBh[nf] = packbf(p2, p3);
        pAl[nf] = packbf(bfres(p0), bfres(p1));
        pBl[nf] = packbf(bfres(p2), bfres(p3));
    }

    float acc2[8][4];
#pragma unroll
    for (int u = 0; u < 8; u++)
#pragma unroll
        for (int i = 0; i < 4; i++) acc2[u][i] = 0.f;

#pragma unroll
    for (int ks = 0; ks < 16; ks++) {
        if (ks >= j0) {
            uint32_t a_h[4] = {pAh[2 * ks], pBh[2 * ks], pAh[2 * ks + 1], pBh[2 * ks + 1]};
            uint32_t a_l[4] = {pAl[2 * ks], pBl[2 * ks], pAl[2 * ks + 1], pBl[2 * ks + 1]};
#pragma unroll
            for (int t = 0; t < 4; t++) {
                uint32_t off = SW128((uint32_t)((ks * 16 + lr) * 128 + t * 32 + lcb));
                uint32_t vh[4], vl[4];
                ldm_x4_t(vh, smb + VFH + off);
                ldm_x4_t(vl, smb + VFL + off);
                mma_bf16(acc2[2 * t],     a_h, vh[0], vh[1]);
                mma_bf16(acc2[2 * t],     a_l, vh[0], vh[1]);
                mma_bf16(acc2[2 * t],     a_h, vl[0], vl[1]);
                mma_bf16(acc2[2 * t + 1], a_h, vh[2], vh[3]);
                mma_bf16(acc2[2 * t + 1], a_l, vh[2], vh[3]);
                mma_bf16(acc2[2 * t + 1], a_h, vl[2], vl[3]);
            }
        }
    }

    float* ob = out + (size_t)b * SS * DD;
#pragma unroll
    for (int u = 0; u < 8; u++) {
        const int d0 = 8 * u + 2 * q;
        *reinterpret_cast<float2*>(&ob[(size_t)rowa * DD + d0]) =
            make_float2(acc2[u][0], acc2[u][1]);
        *reinterpret_cast<float2*>(&ob[(size_t)rowb * DD + d0]) =
            make_float2(acc2[u][2], acc2[u][3]);
    }

    // ---- fused broadcast: rows >= KC get mean_k Vf[k][:] (exact uniform P).
    __syncthreads();
    {
        float* red = reinterpret_cast<float*>(sm + QH);          // [4][64]
        float* meanv = reinterpret_cast<float*>(sm + QH) + 256;  // [64]
        const int dp = tid & 31, kq = tid >> 5;
        float m0 = 0.f, m1 = 0.f;
        for (int k = kq * 64; k < kq * 64 + 64; k++) {
            uint32_t off = SW128((uint32_t)(k * 128 + dp * 4));
            uint32_t hw = *reinterpret_cast<const uint32_t*>(sm + VFH + off);
            uint32_t lw = *reinterpret_cast<const uint32_t*>(sm + VFL + off);
            __nv_bfloat162 hv = *reinterpret_cast<__nv_bfloat162*>(&hw);
            __nv_bfloat162 lv = *reinterpret_cast<__nv_bfloat162*>(&lw);
            m0 += __bfloat162float(hv.x) + __bfloat162float(lv.x);
            m1 += __bfloat162float(hv.y) + __bfloat162float(lv.y);
        }
        red[kq * 64 + 2 * dp]     = m0;
        red[kq * 64 + 2 * dp + 1] = m1;
        __syncthreads();
        if (tid < 64)
            meanv[tid] = (red[tid] + red[64 + tid] + red[128 + tid] +
                          red[192 + tid]) * (1.f / 256.f);
        __syncthreads();

        const int ccol = tid & 15, rofs = tid >> 4;
        const float4 val = make_float4(meanv[ccol * 4], meanv[ccol * 4 + 1],
                                       meanv[ccol * 4 + 2], meanv[ccol * 4 + 3]);
        float4* obv = reinterpret_cast<float4*>(out + (size_t)b * SS * DD);
        const int r0b = KCC + blockIdx.x * 960;
#pragma unroll 4
        for (int r = r0b + rofs; r < r0b + 960; r += 8)
            obv[(size_t)r * 16 + ccol] = val;
    }
}

// ---------------------------------------------------------------------------
// Harness entry. Inputs: Q, K, V, E_w, E_b, F_w, F_b. Output f32 [B,S,D].
// ---------------------------------------------------------------------------
extern "C" void kernel_launch(void* const* d_in, const int* in_sizes, int n_in,
                              void* d_out, int out_size)
{
    (void)in_sizes; (void)n_in; (void)out_size;
    const float* Q   = (const float*)d_in[0];
    const float* K   = (const float*)d_in[1];
    const float* V   = (const float*)d_in[2];
    const float* E_w = (const float*)d_in[3];
    const float* E_b = (const float*)d_in[4];
    const float* F_w = (const float*)d_in[5];
    const float* F_b = (const float*)d_in[6];
    float* out = (float*)d_out;

    const int proj_smem = 163840;   // 160 KB (W 96K + Xf 48K + Xh 16K)
    const int attn_smem = 147456;   // 144 KB
    cudaFuncSetAttribute(proj_mma_kernel,
                         cudaFuncAttributeMaxDynamicSharedMemorySize, proj_smem);
    cudaFuncSetAttribute(attn_kernel,
                         cudaFuncAttributeMaxDynamicSharedMemorySize, attn_smem);

    void* accptr = nullptr;
    cudaGetSymbolAddress(&accptr, g_acc);
    cudaMemsetAsync(accptr, 0, sizeof(float) * 2 * BB * KCC * DD);

    conv_w_kernel<<<dim3(1024, 2), 256>>>(E_w, F_w);
    proj_mma_kernel<<<dim3(2, BB, 2), 256, proj_smem>>>(K, V);
    attn_kernel<<<dim3(4, BB), 128, attn_smem>>>(Q, E_b, F_b, out);
}

// round 13
// speedup vs baseline: 2.4560x; 1.0310x over previous
#include <cuda_runtime.h>
#include <cuda_bf16.h>
#include <cuda_fp16.h>
#include <cstdint>

#define BB 32
#define SS 4096
#define DD 64
#define KCC 256

// ------------------------- device global scratch ---------------------------
__device__ __half g_Wh[2 * KCC * SS];        // [proj][kc][s] fp16
__device__ float  g_acc[2 * BB * KCC * DD];  // [proj][b][kc][d] fp32 partial sums

// ------------------------------ helpers ------------------------------------
__device__ __forceinline__ uint32_t smem_u32(const void* p) {
    uint32_t a;
    asm("{ .reg .u64 t; cvta.to.shared.u64 t, %1; cvt.u32.u64 %0, t; }"
        : "=r"(a) : "l"(p));
    return a;
}
#define SW128(x) ((x) ^ (((x) >> 3) & 0x70))

__device__ __forceinline__ void cp16(uint32_t dst, const void* src) {
    asm volatile("cp.async.cg.shared.global [%0], [%1], 16;"
                 :: "r"(dst), "l"(src) : "memory");
}
__device__ __forceinline__ void cp_commit() {
    asm volatile("cp.async.commit_group;" ::: "memory");
}
template <int N>
__device__ __forceinline__ void cp_wait() {
    asm volatile("cp.async.wait_group %0;" :: "n"(N) : "memory");
}
__device__ __forceinline__ void ldm_x4(uint32_t* r, uint32_t addr) {
    asm volatile("ldmatrix.sync.aligned.m8n8.x4.shared.b16 {%0,%1,%2,%3}, [%4];"
                 : "=r"(r[0]), "=r"(r[1]), "=r"(r[2]), "=r"(r[3]) : "r"(addr));
}
__device__ __forceinline__ void ldm_x4_t(uint32_t* r, uint32_t addr) {
    asm volatile("ldmatrix.sync.aligned.m8n8.x4.trans.shared.b16 {%0,%1,%2,%3}, [%4];"
                 : "=r"(r[0]), "=r"(r[1]), "=r"(r[2]), "=r"(r[3]) : "r"(addr));
}
__device__ __forceinline__ void mma_bf16(
    float* c, const uint32_t* a, uint32_t b0, uint32_t b1) {
    asm volatile(
        "mma.sync.aligned.m16n8k16.row.col.f32.bf16.bf16.f32 "
        "{%0,%1,%2,%3}, {%4,%5,%6,%7}, {%8,%9}, {%0,%1,%2,%3};"
        : "+f"(c[0]), "+f"(c[1]), "+f"(c[2]), "+f"(c[3])
        : "r"(a[0]), "r"(a[1]), "r"(a[2]), "r"(a[3]), "r"(b0), "r"(b1));
}
__device__ __forceinline__ void mma_f16(
    float* c, const uint32_t* a, uint32_t b0, uint32_t b1) {
    asm volatile(
        "mma.sync.aligned.m16n8k16.row.col.f32.f16.f16.f32 "
        "{%0,%1,%2,%3}, {%4,%5,%6,%7}, {%8,%9}, {%0,%1,%2,%3};"
        : "+f"(c[0]), "+f"(c[1]), "+f"(c[2]), "+f"(c[3])
        : "r"(a[0]), "r"(a[1]), "r"(a[2]), "r"(a[3]), "r"(b0), "r"(b1));
}
__device__ __forceinline__ uint32_t packbf(float lo, float hi) {
    uint32_t r;
    asm("cvt.rn.bf16x2.f32 %0, %1, %2;" : "=r"(r) : "f"(hi), "f"(lo));
    return r;
}
__device__ __forceinline__ uint32_t packhf(float lo, float hi) {
    uint32_t r;
    asm("cvt.rn.f16x2.f32 %0, %1, %2;" : "=r"(r) : "f"(hi), "f"(lo));
    return r;
}
__device__ __forceinline__ float bfres(float v) {   // v - bf16(v)
    return v - __bfloat162float(__float2bfloat16(v));
}

// ---------------------------------------------------------------------------
// conv_w: E_w / F_w (fp32 [256][4096]) -> fp16, same layout. Grid (1024, 2).
// ---------------------------------------------------------------------------
__global__ __launch_bounds__(256) void conv_w_kernel(
    const float* __restrict__ Ew, const float* __restrict__ Fw)
{
    const int y = blockIdx.y;
    const float4* src = reinterpret_cast<const float4*>(y ? Fw : Ew);
    const int i = blockIdx.x * 256 + threadIdx.x;
    float4 v = src[i];
    __half2* oh = reinterpret_cast<__half2*>(g_Wh + (size_t)y * KCC * SS) + 2 * i;
    oh[0] = __halves2half2(__float2half(v.x), __float2half(v.y));
    oh[1] = __halves2half2(__float2half(v.z), __float2half(v.w));
}

// ---------------------------------------------------------------------------
// proj_mma: mma.sync fp16 GEMM; s-quarter split + 2 batches per CTA so the
// W stream is shared (halves W L2 traffic, doubles MMA per byte loaded).
//   partial[bb][kc][d] = sum_{s in quarter} Wh[kc][s] * X[bb][s][d]
//   (M=256 kc, N=64 d, K=1024 per CTA, bb=2 batches)
// Grid (4 s-quarters, 16 b-pairs, 2 proj) = 128 CTAs. Block 256
// (2 m-groups x 4 n-groups, warp tile M=128 per batch).
// Epilogue: scalar fp32 atomicAdd into g_acc (4 contributions/element).
// SMEM: W 3x32KB @0 | Xf 3x32KB @98304 | Xh 2x16KB @196608 = 224 KB.
// ---------------------------------------------------------------------------
__global__ __launch_bounds__(256) void proj_mma_kernel(
    const float* __restrict__ Kf, const float* __restrict__ Vf)
{
    extern __shared__ char sm[];
    const uint32_t smb = smem_u32(sm);
    const int tid = threadIdx.x, wid = tid >> 5, lane = tid & 31;
    const int sq = blockIdx.x, bp = blockIdx.y, proj = blockIdx.z;
    const int mw = wid >> 2, nw = wid & 3;
    const int g = lane >> 2, q = lane & 3;

    const __half* Wh = g_Wh + (size_t)proj * KCC * SS;          // full 256 kc
    const float* Xsrc = proj ? Vf : Kf;
    const float* Xb[2] = { Xsrc + (size_t)(2 * bp) * SS * DD,
                           Xsrc + (size_t)(2 * bp + 1) * SS * DD };
    const int sbase = sq * 1024;

    float acc[2][8][2][4];   // [batch][mf][nf][c] = 128 regs
#pragma unroll
    for (int bb = 0; bb < 2; bb++)
#pragma unroll
        for (int mf = 0; mf < 8; mf++)
#pragma unroll
            for (int nf = 0; nf < 2; nf++)
#pragma unroll
                for (int i = 0; i < 4; i++) acc[bb][mf][nf][i] = 0.f;

    const int NC = 1024 / 64;   // 16 chunks per CTA

    auto load_chunk = [&](int c) {
        const uint32_t wbuf = smb + (c % 3) * 32768;
#pragma unroll
        for (int idx = tid; idx < 2048; idx += 256) {           // W: 256 rows
            int row = idx >> 3, s16 = idx & 7;
            size_t so = (size_t)row * SS + sbase + c * 64 + s16 * 8;
            uint32_t bo = SW128((uint32_t)(row * 128 + s16 * 16));
            cp16(wbuf + bo, Wh + so);
        }
        const uint32_t xfbuf = smb + 98304 + (c % 3) * 32768;
#pragma unroll
        for (int bb = 0; bb < 2; bb++) {
            const float* xsrc = Xb[bb] + (size_t)(sbase + c * 64) * DD;
#pragma unroll
            for (int u = 0; u < 2; u++) {
                int seg = tid + u * 256;                        // 32B segments
                cp16(xfbuf + bb * 16384 + seg * 32,      xsrc + seg * 8);
                cp16(xfbuf + bb * 16384 + seg * 32 + 16, xsrc + seg * 8 + 4);
            }
        }
        cp_commit();
    };

    // X fp32 (linear) -> fp16 (swizzled); own-thread segments only
    auto convert_x = [&](int c) {
        const char* xf = sm + 98304 + (c % 3) * 32768;
        char* xbb = sm + 196608 + (c & 1) * 16384;
#pragma unroll
        for (int bb = 0; bb < 2; bb++)
#pragma unroll
            for (int u = 0; u < 2; u++) {
                int seg = tid + u * 256;
                int row = seg >> 3, s16 = seg & 7;
                float4 v0 = *reinterpret_cast<const float4*>(
                    xf + bb * 16384 + seg * 32);
                float4 v1 = *reinterpret_cast<const float4*>(
                    xf + bb * 16384 + seg * 32 + 16);
                uint32_t bo = SW128((uint32_t)(row * 128 + s16 * 16));
                uint4 h;
                h.x = packhf(v0.x, v0.y); h.y = packhf(v0.z, v0.w);
                h.z = packhf(v1.x, v1.y); h.w = packhf(v1.z, v1.w);
                *reinterpret_cast<uint4*>(xbb + bb * 8192 + bo) = h;
            }
    };

    load_chunk(0); load_chunk(1);

    for (int c = 0; c < NC; c++) {
        if (c + 2 < NC) { load_chunk(c + 2); cp_wait<2>(); }
        else            { cp_wait<0>(); }

        convert_x(c);
        __syncthreads();   // W stage + Xh visible to all warps

        const uint32_t Ah = smb + (c % 3) * 32768;
        const uint32_t Xh = smb + 196608 + (c & 1) * 16384;
        const int lr = lane & 15, lc = (lane >> 4) * 16;

#pragma unroll
        for (int kk = 0; kk < 4; kk++) {
            uint32_t bh[2][4];
            uint32_t boff = SW128((uint32_t)((kk * 16 + lr) * 128 + nw * 32 + lc));
            ldm_x4_t(bh[0], Xh + boff);
            ldm_x4_t(bh[1], Xh + 8192 + boff);
#pragma unroll
            for (int mf = 0; mf < 8; mf++) {
                uint32_t ah[4];
                uint32_t off = SW128((uint32_t)(
                    (mw * 128 + mf * 16 + lr) * 128 + kk * 32 + lc));
                ldm_x4(ah, Ah + off);
#pragma unroll
                for (int bb = 0; bb < 2; bb++)
#pragma unroll
                    for (int nf = 0; nf < 2; nf++)
                        mma_f16(acc[bb][mf][nf], ah,
                                bh[bb][2 * nf], bh[bb][2 * nf + 1]);
            }
        }
        __syncthreads();   // all MMA(c) done before stage reuse
    }

    // ---- epilogue: atomic accumulate fp32 partials into g_acc ----
#pragma unroll
    for (int bb = 0; bb < 2; bb++) {
        float* out = g_acc + ((size_t)proj * BB + 2 * bp + bb) * KCC * DD;
#pragma unroll
        for (int mf = 0; mf < 8; mf++) {
            const int kcl = mw * 128 + mf * 16 + g;
#pragma unroll
            for (int nf = 0; nf < 2; nf++) {
                const int d0 = nw * 16 + nf * 8 + 2 * q;
                atomicAdd(&out[(size_t)kcl * DD + d0],           acc[bb][mf][nf][0]);
                atomicAdd(&out[(size_t)kcl * DD + d0 + 1],       acc[bb][mf][nf][1]);
                atomicAdd(&out[(size_t)(kcl + 8) * DD + d0],     acc[bb][mf][nf][2]);
                atomicAdd(&out[(size_t)(kcl + 8) * DD + d0 + 1], acc[bb][mf][nf][3]);
            }
        }
    }
}

// ---------------------------------------------------------------------------
// attn: tensor-core fused attention (rows 0..255) + fused broadcast of the
// fully-masked rows (256..4095 = column mean of Vf, exactly uniform softmax).
// Loads Ke/Vf as fp32 from g_acc (adds bias) and splits to bf16 hi/lo in the
// loader. Grid (4, B). Block 128 (4 warps x 16 rows).
// SMEM: Ke h/l 64K | Vf h/l 64K | Q h/l 16K = 144KB.
// ---------------------------------------------------------------------------
__global__ __launch_bounds__(128) void attn_kernel(
    const float* __restrict__ Qf,
    const float* __restrict__ E_b, const float* __restrict__ F_b,
    float* __restrict__ out)
{
    extern __shared__ char sm[];
    const uint32_t smb = smem_u32(sm);
    const uint32_t KEH = 0, KEL = 32768, VFH = 65536, VFL = 98304,
                   QH = 131072, QL = 139264;

    const int tid = threadIdx.x, lane = tid & 31, warp = tid >> 5;
    const int b = blockIdx.y;
    const int s0 = blockIdx.x * 64;
    const int g = lane >> 2, q = lane & 3;
    const int lr = lane & 15, lcb = (lane >> 4) * 16;

    // ---- Ke / Vf: fp32 from g_acc (+ bias) -> bf16 hi/lo smem tiles ----
    {
        const float* keA = g_acc + (size_t)b * KCC * DD;                 // proj 0
        const float* vfA = g_acc + ((size_t)BB + b) * KCC * DD;          // proj 1
#pragma unroll
        for (int idx = tid; idx < 2048; idx += 128) {
            int row = idx >> 3, seg = idx & 7;
            uint32_t bo = SW128((uint32_t)(row * 128 + seg * 16));
            {
                const float* p = keA + (size_t)row * DD + seg * 8;
                float bv = E_b[row];
                float4 v0 = *reinterpret_cast<const float4*>(p);
                float4 v1 = *reinterpret_cast<const float4*>(p + 4);
                v0.x += bv; v0.y += bv; v0.z += bv; v0.w += bv;
                v1.x += bv; v1.y += bv; v1.z += bv; v1.w += bv;
                uint4 h, l;
                h.x = packbf(v0.x, v0.y); h.y = packbf(v0.z, v0.w);
                h.z = packbf(v1.x, v1.y); h.w = packbf(v1.z, v1.w);
                l.x = packbf(bfres(v0.x), bfres(v0.y));
                l.y = packbf(bfres(v0.z), bfres(v0.w));
                l.z = packbf(bfres(v1.x), bfres(v1.y));
                l.w = packbf(bfres(v1.z), bfres(v1.w));
                *reinterpret_cast<uint4*>(sm + KEH + bo) = h;
                *reinterpret_cast<uint4*>(sm + KEL + bo) = l;
            }
            {
                const float* p = vfA + (size_t)row * DD + seg * 8;
                float bv = F_b[row];
                float4 v0 = *reinterpret_cast<const float4*>(p);
                float4 v1 = *reinterpret_cast<const float4*>(p + 4);
                v0.x += bv; v0.y += bv; v0.z += bv; v0.w += bv;
                v1.x += bv; v1.y += bv; v1.z += bv; v1.w += bv;
                uint4 h, l;
                h.x = packbf(v0.x, v0.y); h.y = packbf(v0.z, v0.w);
                h.z = packbf(v1.x, v1.y); h.w = packbf(v1.z, v1.w);
                l.x = packbf(bfres(v0.x), bfres(v0.y));
                l.y = packbf(bfres(v0.z), bfres(v0.w));
                l.z = packbf(bfres(v1.x), bfres(v1.y));
                l.w = packbf(bfres(v1.z), bfres(v1.w));
                *reinterpret_cast<uint4*>(sm + VFH + bo) = h;
                *reinterpret_cast<uint4*>(sm + VFL + bo) = l;
            }
        }
    }
    // ---- Q: fp32 -> bf16 hi/lo smem ----
    {
        const float* qb = Qf + ((size_t)b * SS + s0) * DD;
#pragma unroll
        for (int idx = tid; idx < 512; idx += 128) {
            int row = idx >> 3, seg = idx & 7;
            const float* qp = qb + (size_t)row * DD + seg * 8;
            float4 v0 = *reinterpret_cast<const float4*>(qp);
            float4 v1 = *reinterpret_cast<const float4*>(qp + 4);
            uint32_t bo = SW128((uint32_t)(row * 128 + seg * 16));
            uint4 h, l;
            h.x = packbf(v0.x, v0.y); h.y = packbf(v0.z, v0.w);
            h.z = packbf(v1.x, v1.y); h.w = packbf(v1.z, v1.w);
            l.x = packbf(bfres(v0.x), bfres(v0.y));
            l.y = packbf(bfres(v0.z), bfres(v0.w));
            l.z = packbf(bfres(v1.x), bfres(v1.y));
            l.w = packbf(bfres(v1.z), bfres(v1.w));
            *reinterpret_cast<uint4*>(sm + QH + bo) = h;
            *reinterpret_cast<uint4*>(sm + QL + bo) = l;
        }
    }
    __syncthreads();

    const int j0 = blockIdx.x * 4 + warp;   // first possibly-unmasked kc tile

    float acc[32][4];
#pragma unroll
    for (int nf = 0; nf < 32; nf++)
#pragma unroll
        for (int i = 0; i < 4; i++) acc[nf][i] = 0.f;

#pragma unroll
    for (int kk = 0; kk < 4; kk++) {
        uint32_t qh[4], ql[4];
        uint32_t offA = SW128((uint32_t)((warp * 16 + lr) * 128 + kk * 32 + lcb));
        ldm_x4(qh, smb + QH + offA);
        ldm_x4(ql, smb + QL + offA);
#pragma unroll
        for (int j = 0; j < 16; j++) {
            if (j >= j0) {
                uint32_t off = SW128((uint32_t)((j * 16 + lr) * 128 + kk * 32 + lcb));
                uint32_t bh[4], bl[4];
                ldm_x4(bh, smb + KEH + off);
                ldm_x4(bl, smb + KEL + off);
                mma_bf16(acc[2 * j],     qh, bh[0], bh[2]);
                mma_bf16(acc[2 * j],     ql, bh[0], bh[2]);
                mma_bf16(acc[2 * j],     qh, bl[0], bl[2]);
                mma_bf16(acc[2 * j + 1], qh, bh[1], bh[3]);
                mma_bf16(acc[2 * j + 1], ql, bh[1], bh[3]);
                mma_bf16(acc[2 * j + 1], qh, bl[1], bl[3]);
            }
        }
    }

    const int rowa = s0 + warp * 16 + g;
    const int rowb = rowa + 8;
    float mxa = -3.4e38f, mxb = -3.4e38f;
#pragma unroll
    for (int nf = 0; nf < 32; nf++) {
        const int kc = 8 * nf + 2 * q;
        acc[nf][0] = (kc     >= rowa) ? acc[nf][0] * 0.125f : -1e10f;
        acc[nf][1] = (kc + 1 >= rowa) ? acc[nf][1] * 0.125f : -1e10f;
        acc[nf][2] = (kc     >= rowb) ? acc[nf][2] * 0.125f : -1e10f;
        acc[nf][3] = (kc + 1 >= rowb) ? acc[nf][3] * 0.125f : -1e10f;
        mxa = fmaxf(mxa, fmaxf(acc[nf][0], acc[nf][1]));
        mxb = fmaxf(mxb, fmaxf(acc[nf][2], acc[nf][3]));
    }
#pragma unroll
    for (int o = 1; o <= 2; o <<= 1) {
        mxa = fmaxf(mxa, __shfl_xor_sync(0xffffffffu, mxa, o));
        mxb = fmaxf(mxb, __shfl_xor_sync(0xffffffffu, mxb, o));
    }
    float sa = 0.f, sb = 0.f;
#pragma unroll
    for (int nf = 0; nf < 32; nf++) {
        acc[nf][0] = __expf(acc[nf][0] - mxa);
        acc[nf][1] = __expf(acc[nf][1] - mxa);
        acc[nf][2] = __expf(acc[nf][2] - mxb);
        acc[nf][3] = __expf(acc[nf][3] - mxb);
        sa += acc[nf][0] + acc[nf][1];
        sb += acc[nf][2] + acc[nf][3];
    }
#pragma unroll
    for (int o = 1; o <= 2; o <<= 1) {
        sa += __shfl_xor_sync(0xffffffffu, sa, o);
        sb += __shfl_xor_sync(0xffffffffu, sb, o);
    }
    const float inva = 1.f / sa, invb = 1.f / sb;

    uint32_t pAh[32], pAl[32], pBh[32], pBl[32];
#pragma unroll
    for (int nf = 0; nf < 32; nf++) {
        float p0 = acc[nf][0] * inva, p1 = acc[nf][1] * inva;
        float p2 = acc[nf][2] * invb, p3 = acc[nf][3] * invb;
        pAh[nf] = packbf(p0, p1);
        pBh[nf] = packbf(p2, p3);
        pAl[nf] = packbf(bfres(p0), bfres(p1));
        pBl[nf] = packbf(bfres(p2), bfres(p3));
    }

    float acc2[8][4];
#pragma unroll
    for (int u = 0; u < 8; u++)
#pragma unroll
        for (int i = 0; i < 4; i++) acc2[u][i] = 0.f;

#pragma unroll
    for (int ks = 0; ks < 16; ks++) {
        if (ks >= j0) {
            uint32_t a_h[4] = {pAh[2 * ks], pBh[2 * ks], pAh[2 * ks + 1], pBh[2 * ks + 1]};
            uint32_t a_l[4] = {pAl[2 * ks], pBl[2 * ks], pAl[2 * ks + 1], pBl[2 * ks + 1]};
#pragma unroll
            for (int t = 0; t < 4; t++) {
                uint32_t off = SW128((uint32_t)((ks * 16 + lr) * 128 + t * 32 + lcb));
                uint32_t vh[4], vl[4];
                ldm_x4_t(vh, smb + VFH + off);
                ldm_x4_t(vl, smb + VFL + off);
                mma_bf16(acc2[2 * t],     a_h, vh[0], vh[1]);
                mma_bf16(acc2[2 * t],     a_l, vh[0], vh[1]);
                mma_bf16(acc2[2 * t],     a_h, vl[0], vl[1]);
                mma_bf16(acc2[2 * t + 1], a_h, vh[2], vh[3]);
                mma_bf16(acc2[2 * t + 1], a_l, vh[2], vh[3]);
                mma_bf16(acc2[2 * t + 1], a_h, vl[2], vl[3]);
            }
        }
    }

    float* ob = out + (size_t)b * SS * DD;
#pragma unroll
    for (int u = 0; u < 8; u++) {
        const int d0 = 8 * u + 2 * q;
        *reinterpret_cast<float2*>(&ob[(size_t)rowa * DD + d0]) =
            make_float2(acc2[u][0], acc2[u][1]);
        *reinterpret_cast<float2*>(&ob[(size_t)rowb * DD + d0]) =
            make_float2(acc2[u][2], acc2[u][3]);
    }

    // ---- fused broadcast: rows >= KC get mean_k Vf[k][:] (exact uniform P).
    __syncthreads();
    {
        float* red = reinterpret_cast<float*>(sm + QH);          // [4][64]
        float* meanv = reinterpret_cast<float*>(sm + QH) + 256;  // [64]
        const int dp = tid & 31, kq = tid >> 5;
        float m0 = 0.f, m1 = 0.f;
        for (int k = kq * 64; k < kq * 64 + 64; k++) {
            uint32_t off = SW128((uint32_t)(k * 128 + dp * 4));
            uint32_t hw = *reinterpret_cast<const uint32_t*>(sm + VFH + off);
            uint32_t lw = *reinterpret_cast<const uint32_t*>(sm + VFL + off);
            __nv_bfloat162 hv = *reinterpret_cast<__nv_bfloat162*>(&hw);
            __nv_bfloat162 lv = *reinterpret_cast<__nv_bfloat162*>(&lw);
            m0 += __bfloat162float(hv.x) + __bfloat162float(lv.x);
            m1 += __bfloat162float(hv.y) + __bfloat162float(lv.y);
        }
        red[kq * 64 + 2 * dp]     = m0;
        red[kq * 64 + 2 * dp + 1] = m1;
        __syncthreads();
        if (tid < 64)
            meanv[tid] = (red[tid] + red[64 + tid] + red[128 + tid] +
                          red[192 + tid]) * (1.f / 256.f);
        __syncthreads();

        const int ccol = tid & 15, rofs = tid >> 4;
        const float4 val = make_float4(meanv[ccol * 4], meanv[ccol * 4 + 1],
                                       meanv[ccol * 4 + 2], meanv[ccol * 4 + 3]);
        float4* obv = reinterpret_cast<float4*>(out + (size_t)b * SS * DD);
        const int r0b = KCC + blockIdx.x * 960;
#pragma unroll 4
        for (int r = r0b + rofs; r < r0b + 960; r += 8)
            obv[(size_t)r * 16 + ccol] = val;
    }
}

// ---------------------------------------------------------------------------
// Harness entry. Inputs: Q, K, V, E_w, E_b, F_w, F_b. Output f32 [B,S,D].
// ---------------------------------------------------------------------------
extern "C" void kernel_launch(void* const* d_in, const int* in_sizes, int n_in,
                              void* d_out, int out_size)
{
    (void)in_sizes; (void)n_in; (void)out_size;
    const float* Q   = (const float*)d_in[0];
    const float* K   = (const float*)d_in[1];
    const float* V   = (const float*)d_in[2];
    const float* E_w = (const float*)d_in[3];
    const float* E_b = (const float*)d_in[4];
    const float* F_w = (const float*)d_in[5];
    const float* F_b = (const float*)d_in[6];
    float* out = (float*)d_out;

    const int proj_smem = 229376;   // 224 KB (W 96K + Xf 96K + Xh 32K)
    const int attn_smem = 147456;   // 144 KB
    cudaFuncSetAttribute(proj_mma_kernel,
                         cudaFuncAttributeMaxDynamicSharedMemorySize, proj_smem);
    cudaFuncSetAttribute(attn_kernel,
                         cudaFuncAttributeMaxDynamicSharedMemorySize, attn_smem);

    void* accptr = nullptr;
    cudaGetSymbolAddress(&accptr, g_acc);
    cudaMemsetAsync(accptr, 0, sizeof(float) * 2 * BB * KCC * DD);

    conv_w_kernel<<<dim3(1024, 2), 256>>>(E_w, F_w);
    proj_mma_kernel<<<dim3(4, BB / 2, 2), 256, proj_smem>>>(K, V);
    attn_kernel<<<dim3(4, BB), 128, attn_smem>>>(Q, E_b, F_b, out);
}